// round 1
// baseline (speedup 1.0000x reference)
#include <cuda_runtime.h>
#include <math.h>

// ---------------------------------------------------------------------------
// Problem constants
// ---------------------------------------------------------------------------
#define BB 8
#define TT 8
#define HH 56
#define WW2 56
#define CC 128
#define NHH 4
#define HDD 32
#define NTOK 98           // tokens per window (2*7*7)
#define NWIN 256          // windows per batch (4*8*8)
#define BWIN 2048         // total windows
#define LTOK 25088        // T*H*W
#define MROWS 200704      // B*L = BWIN*NTOK
#define HID 512
#define SCALE 0.17677669529663687f
#define EPS 1e-5f

// ---------------------------------------------------------------------------
// Scratch (static device globals; allocation in kernel_launch is forbidden)
// ---------------------------------------------------------------------------
__device__ float g_bufA[(size_t)MROWS * HID];   // qkv (384 cols) then ffn hidden (512)
__device__ float g_bufB[(size_t)MROWS * CC];    // ln1-windowed, attn_out, x2
__device__ float g_bufC[(size_t)MROWS * CC];    // proj_out, ln2_out
__device__ float g_biasNN[NHH * NTOK * NTOK];   // expanded relative position bias

// ---------------------------------------------------------------------------
// Relative-position-bias expansion: bias[h][i][j] = rpb[relidx(i,j)*NH + h]
// ---------------------------------------------------------------------------
__global__ void bias_expand_kernel(const float* __restrict__ rpb) {
    int idx = blockIdx.x * blockDim.x + threadIdx.x;
    if (idx >= NHH * NTOK * NTOK) return;
    int h = idx / (NTOK * NTOK);
    int r = idx % (NTOK * NTOK);
    int i = r / NTOK, j = r % NTOK;
    int ti = i / 49, hi = (i / 7) % 7, wi = i % 7;
    int tj = j / 49, hj = (j / 7) % 7, wj = j % 7;
    int dt = ti - tj + 1;        // 0..2
    int dh = hi - hj + 6;        // 0..12
    int dw = wi - wj + 6;        // 0..12
    int ridx = dt * 169 + dh * 13 + dw;
    g_biasNN[idx] = rpb[ridx * NHH + h];
}

// ---------------------------------------------------------------------------
// LN1 + cyclic shift + window partition. One warp per output window-token row.
// out[row, c] where row = bwin*98 + n  (window layout)
// ---------------------------------------------------------------------------
__global__ void ln_gather_kernel(const float* __restrict__ x,
                                 const float* __restrict__ g,
                                 const float* __restrict__ bta,
                                 float* __restrict__ out) {
    int warp = threadIdx.x >> 5, lane = threadIdx.x & 31;
    int row = blockIdx.x * 8 + warp;            // 0..MROWS-1
    int bwin = row / NTOK, n = row % NTOK;
    int b = bwin >> 8, win = bwin & 255;
    int tw = win >> 6, hw = (win >> 3) & 7, ww = win & 7;
    int t0 = n / 49, r49 = n % 49, h0 = r49 / 7, w0 = r49 % 7;
    int tg = (tw * 2 + t0 + 1) & 7;             // roll by -1 on T
    int hg = hw * 7 + h0 + 3; if (hg >= 56) hg -= 56;
    int wg = ww * 7 + w0 + 3; if (wg >= 56) wg -= 56;
    const float* src = x + ((size_t)b * LTOK + (size_t)(tg * 56 + hg) * 56 + wg) * CC;

    float v[4]; float s = 0.f;
#pragma unroll
    for (int k = 0; k < 4; k++) { v[k] = src[lane + 32 * k]; s += v[k]; }
#pragma unroll
    for (int o = 16; o > 0; o >>= 1) s += __shfl_xor_sync(0xffffffffu, s, o);
    float mean = s * (1.0f / CC);
    float q = 0.f;
#pragma unroll
    for (int k = 0; k < 4; k++) { float d = v[k] - mean; q += d * d; }
#pragma unroll
    for (int o = 16; o > 0; o >>= 1) q += __shfl_xor_sync(0xffffffffu, q, o);
    float rstd = rsqrtf(q * (1.0f / CC) + EPS);

    float* dst = out + (size_t)row * CC;
#pragma unroll
    for (int k = 0; k < 4; k++) {
        int c = lane + 32 * k;
        dst[c] = (v[k] - mean) * rstd * g[c] + bta[c];
    }
}

// ---------------------------------------------------------------------------
// Plain LayerNorm (one warp per row)
// ---------------------------------------------------------------------------
__global__ void ln_kernel(const float* __restrict__ in,
                          const float* __restrict__ g,
                          const float* __restrict__ bta,
                          float* __restrict__ out) {
    int warp = threadIdx.x >> 5, lane = threadIdx.x & 31;
    int row = blockIdx.x * 8 + warp;
    const float* src = in + (size_t)row * CC;
    float v[4]; float s = 0.f;
#pragma unroll
    for (int k = 0; k < 4; k++) { v[k] = src[lane + 32 * k]; s += v[k]; }
#pragma unroll
    for (int o = 16; o > 0; o >>= 1) s += __shfl_xor_sync(0xffffffffu, s, o);
    float mean = s * (1.0f / CC);
    float q = 0.f;
#pragma unroll
    for (int k = 0; k < 4; k++) { float d = v[k] - mean; q += d * d; }
#pragma unroll
    for (int o = 16; o > 0; o >>= 1) q += __shfl_xor_sync(0xffffffffu, q, o);
    float rstd = rsqrtf(q * (1.0f / CC) + EPS);
    float* dst = out + (size_t)row * CC;
#pragma unroll
    for (int k = 0; k < 4; k++) {
        int c = lane + 32 * k;
        dst[c] = (v[k] - mean) * rstd * g[c] + bta[c];
    }
}

// ---------------------------------------------------------------------------
// Generic tiled GEMM: out[M,N] = A[M,K] @ W[K,N] + bias  (+ epilogue)
// epi: 0 = bias, 1 = bias + exact GELU, 2 = bias + resid add
// BM=BN=64, BK=16, 256 threads, 4x4 per-thread micro-tile.
// Assumes M%64==0, N%64==0, K%16==0 (true for all calls here).
// ---------------------------------------------------------------------------
__global__ void gemm_kernel(const float* __restrict__ A,
                            const float* __restrict__ W,
                            const float* __restrict__ bias,
                            const float* __restrict__ resid,
                            float* __restrict__ out,
                            int M, int Np, int K, int epi) {
    __shared__ __align__(16) float As[64 * 17];
    __shared__ __align__(16) float Ws[16 * 64];

    int t = threadIdx.x;
    int tx = t & 15, ty = t >> 4;
    int n0 = blockIdx.x * 64;
    int m0 = blockIdx.y * 64;

    float acc[4][4];
#pragma unroll
    for (int e = 0; e < 4; e++)
#pragma unroll
        for (int f = 0; f < 4; f++) acc[e][f] = 0.f;

    int akk = t & 15, arow = t >> 4;     // A-tile load pattern
    int wj = t & 63, wkb = t >> 6;       // W-tile load pattern

    for (int kt = 0; kt < K; kt += 16) {
#pragma unroll
        for (int p = 0; p < 4; p++) {
            int row = arow + p * 16;
            As[row * 17 + akk] = A[(size_t)(m0 + row) * K + kt + akk];
        }
#pragma unroll
        for (int p = 0; p < 4; p++) {
            int kk = wkb * 4 + p;
            Ws[kk * 64 + wj] = W[(size_t)(kt + kk) * Np + n0 + wj];
        }
        __syncthreads();
#pragma unroll
        for (int kk = 0; kk < 16; kk++) {
            float4 bv = *(const float4*)&Ws[kk * 64 + tx * 4];
            float a0 = As[(ty * 4 + 0) * 17 + kk];
            float a1 = As[(ty * 4 + 1) * 17 + kk];
            float a2 = As[(ty * 4 + 2) * 17 + kk];
            float a3 = As[(ty * 4 + 3) * 17 + kk];
            acc[0][0] += a0 * bv.x; acc[0][1] += a0 * bv.y; acc[0][2] += a0 * bv.z; acc[0][3] += a0 * bv.w;
            acc[1][0] += a1 * bv.x; acc[1][1] += a1 * bv.y; acc[1][2] += a1 * bv.z; acc[1][3] += a1 * bv.w;
            acc[2][0] += a2 * bv.x; acc[2][1] += a2 * bv.y; acc[2][2] += a2 * bv.z; acc[2][3] += a2 * bv.w;
            acc[3][0] += a3 * bv.x; acc[3][1] += a3 * bv.y; acc[3][2] += a3 * bv.z; acc[3][3] += a3 * bv.w;
        }
        __syncthreads();
    }

    int mB = m0 + ty * 4, nB = n0 + tx * 4;
#pragma unroll
    for (int e = 0; e < 4; e++) {
        size_t rowoff = (size_t)(mB + e) * Np;
#pragma unroll
        for (int f = 0; f < 4; f++) {
            float v = acc[e][f] + bias[nB + f];
            if (epi == 1) {
                v = 0.5f * v * (1.0f + erff(v * 0.7071067811865475f));
            } else if (epi == 2) {
                v += resid[rowoff + nB + f];
            }
            out[rowoff + nB + f] = v;
        }
    }
}

// ---------------------------------------------------------------------------
// Attention: one CTA per (window, head). 128 threads.
// qkv layout: [BWIN*98, 384], col = {q,k,v}*128 + head*32 + d
// out layout: [BWIN*98, 128] (head-concat), ready for proj GEMM.
// smem: q/k/v padded to 33 floats/row, plus full 98x98 score matrix.
// ---------------------------------------------------------------------------
#define ATTN_SMEM_FLOATS (3 * 98 * 33 + 98 * 98)

__global__ void attn_kernel(const float* __restrict__ qkv,
                            float* __restrict__ out) {
    extern __shared__ float sm[];
    float* sq = sm;
    float* sk = sm + 98 * 33;
    float* sv = sm + 2 * 98 * 33;
    float* ss = sm + 3 * 98 * 33;
    __shared__ int sreg[98];

    int bwin = blockIdx.x >> 2;
    int head = blockIdx.x & 3;
    int tid = threadIdx.x;

    size_t base = (size_t)bwin * NTOK * 384 + head * 32;
    for (int idx = tid; idx < 98 * 32; idx += 128) {
        int n = idx >> 5, d = idx & 31;
        size_t o = base + (size_t)n * 384 + d;
        sq[n * 33 + d] = qkv[o] * SCALE;
        sk[n * 33 + d] = qkv[o + 128];
        sv[n * 33 + d] = qkv[o + 256];
    }
    if (tid < 98) {
        int win = bwin & 255;
        int tw = win >> 6, hw = (win >> 3) & 7, ww = win & 7;
        int t0 = tid / 49, r = tid % 49, h0 = r / 7, w0 = r % 7;
        int tg = tw * 2 + t0, hg = hw * 7 + h0, wg = ww * 7 + w0;
        int rt = tg < 6 ? 0 : (tg < 7 ? 1 : 2);
        int rh = hg < 49 ? 0 : (hg < 53 ? 1 : 2);
        int rw = wg < 49 ? 0 : (wg < 53 ? 1 : 2);
        sreg[tid] = rt * 9 + rh * 3 + rw;
    }
    __syncthreads();

    // S = q k^T + bias + mask   (7 columns per thread-iteration)
    const float* bh = g_biasNN + head * (NTOK * NTOK);
    for (int idx = tid; idx < 98 * 14; idx += 128) {
        int i = idx / 14, jg = idx % 14;
        int j0 = jg * 7;
        float acc[7];
#pragma unroll
        for (int u = 0; u < 7; u++) acc[u] = 0.f;
#pragma unroll
        for (int kk = 0; kk < 32; kk++) {
            float qa = sq[i * 33 + kk];
#pragma unroll
            for (int u = 0; u < 7; u++)
                acc[u] += qa * sk[(j0 + u) * 33 + kk];
        }
        int ri = sreg[i];
#pragma unroll
        for (int u = 0; u < 7; u++) {
            int j = j0 + u;
            float m = (ri != sreg[j]) ? -100.0f : 0.0f;
            ss[i * 98 + j] = acc[u] + bh[i * 98 + j] + m;
        }
    }
    __syncthreads();

    // softmax per row
    if (tid < 98) {
        float* row = ss + tid * 98;
        float mx = -1e30f;
        for (int j = 0; j < 98; j++) mx = fmaxf(mx, row[j]);
        float sum = 0.f;
        for (int j = 0; j < 98; j++) { float e = __expf(row[j] - mx); row[j] = e; sum += e; }
        float inv = 1.0f / sum;
        for (int j = 0; j < 98; j++) row[j] *= inv;
    }
    __syncthreads();

    // O = P @ V   (8 head-dims per thread-iteration)
    size_t obase = (size_t)bwin * NTOK * CC + head * 32;
    for (int idx = tid; idx < 98 * 4; idx += 128) {
        int i = idx >> 2, dg = idx & 3;
        int d0 = dg * 8;
        float acc[8];
#pragma unroll
        for (int e = 0; e < 8; e++) acc[e] = 0.f;
        for (int m = 0; m < 98; m++) {
            float p = ss[i * 98 + m];
#pragma unroll
            for (int e = 0; e < 8; e++)
                acc[e] += p * sv[m * 33 + d0 + e];
        }
#pragma unroll
        for (int e = 0; e < 8; e++)
            out[obase + (size_t)i * CC + d0 + e] = acc[e];
    }
}

// ---------------------------------------------------------------------------
// window_reverse + roll(+SS) + shortcut add: x2 = x + scatter(proj_out)
// One warp per token row in (b, l) layout.
// ---------------------------------------------------------------------------
__global__ void scatter_resid_kernel(const float* __restrict__ x,
                                     const float* __restrict__ projout,
                                     float* __restrict__ out) {
    int warp = threadIdx.x >> 5, lane = threadIdx.x & 31;
    int row = blockIdx.x * 8 + warp;           // token row (b*L + l)
    int b = row / LTOK, l = row % LTOK;
    int tg = l / 3136, rem = l % 3136;
    int hg = rem / 56, wg = rem % 56;
    int tp = (tg + 7) & 7;
    int hp = hg - 3; if (hp < 0) hp += 56;
    int wp = wg - 3; if (wp < 0) wp += 56;
    int win = (tp >> 1) * 64 + (hp / 7) * 8 + (wp / 7);
    int n = (tp & 1) * 49 + (hp % 7) * 7 + (wp % 7);
    const float* src = projout + ((size_t)(b * NWIN + win) * NTOK + n) * CC;
    const float* xr = x + (size_t)row * CC;
    float* dst = out + (size_t)row * CC;
#pragma unroll
    for (int k = 0; k < 4; k++) {
        int c = lane + 32 * k;
        dst[c] = xr[c] + src[c];
    }
}

// ---------------------------------------------------------------------------
// Launch
// ---------------------------------------------------------------------------
extern "C" void kernel_launch(void* const* d_in, const int* in_sizes, int n_in,
                              void* d_out, int out_size) {
    const float* x       = (const float*)d_in[0];
    const float* norm1_g = (const float*)d_in[1];
    const float* norm1_b = (const float*)d_in[2];
    const float* qkv_w   = (const float*)d_in[3];
    const float* qkv_b   = (const float*)d_in[4];
    const float* proj_w  = (const float*)d_in[5];
    const float* proj_b  = (const float*)d_in[6];
    const float* rpb     = (const float*)d_in[7];
    const float* norm2_g = (const float*)d_in[8];
    const float* norm2_b = (const float*)d_in[9];
    const float* fc1_w   = (const float*)d_in[10];
    const float* fc1_b   = (const float*)d_in[11];
    const float* fc2_w   = (const float*)d_in[12];
    const float* fc2_b   = (const float*)d_in[13];
    float* outp = (float*)d_out;

    float *bufA, *bufB, *bufC;
    cudaGetSymbolAddress((void**)&bufA, g_bufA);
    cudaGetSymbolAddress((void**)&bufB, g_bufB);
    cudaGetSymbolAddress((void**)&bufC, g_bufC);

    static int smem_set = 0;
    (void)smem_set;
    cudaFuncSetAttribute(attn_kernel, cudaFuncAttributeMaxDynamicSharedMemorySize,
                         ATTN_SMEM_FLOATS * sizeof(float));

    // 1. relative position bias expansion
    bias_expand_kernel<<<(NHH * NTOK * NTOK + 255) / 256, 256>>>(rpb);

    // 2. LN1 + shift + window partition  -> bufB [MROWS, 128]
    ln_gather_kernel<<<MROWS / 8, 256>>>(x, norm1_g, norm1_b, bufB);

    // 3. QKV GEMM -> bufA [MROWS, 384]
    {
        dim3 grid(384 / 64, MROWS / 64);
        gemm_kernel<<<grid, 256>>>(bufB, qkv_w, qkv_b, nullptr, bufA,
                                   MROWS, 384, 128, 0);
    }

    // 4. attention -> bufB [MROWS, 128]
    attn_kernel<<<BWIN * NHH, 128, ATTN_SMEM_FLOATS * sizeof(float)>>>(bufA, bufB);

    // 5. proj GEMM -> bufC [MROWS, 128]
    {
        dim3 grid(128 / 64, MROWS / 64);
        gemm_kernel<<<grid, 256>>>(bufB, proj_w, proj_b, nullptr, bufC,
                                   MROWS, 128, 128, 0);
    }

    // 6. window reverse + roll + shortcut -> bufB = x2
    scatter_resid_kernel<<<MROWS / 8, 256>>>(x, bufC, bufB);

    // 7. LN2 -> bufC
    ln_kernel<<<MROWS / 8, 256>>>(bufB, norm2_g, norm2_b, bufC);

    // 8. FC1 + GELU -> bufA [MROWS, 512]
    {
        dim3 grid(512 / 64, MROWS / 64);
        gemm_kernel<<<grid, 256>>>(bufC, fc1_w, fc1_b, nullptr, bufA,
                                   MROWS, 512, 128, 1);
    }

    // 9. FC2 + residual(x2) -> d_out
    {
        dim3 grid(128 / 64, MROWS / 64);
        gemm_kernel<<<grid, 256>>>(bufA, fc2_w, fc2_b, bufB, outp,
                                   MROWS, 128, 512, 2);
    }
}

// round 2
// speedup vs baseline: 1.3276x; 1.3276x over previous
#include <cuda_runtime.h>
#include <math.h>

// ---------------------------------------------------------------------------
// Problem constants
// ---------------------------------------------------------------------------
#define CC 128
#define NTOK 98
#define NWIN 256
#define BWIN 2048
#define LTOK 25088
#define MROWS 200704
#define HID 512
#define SCALE 0.17677669529663687f
#define EPS 1e-5f

typedef unsigned long long ull;

// ---------------------------------------------------------------------------
// Scratch
// ---------------------------------------------------------------------------
__device__ float g_bufA[(size_t)MROWS * HID];
__device__ float g_bufB[(size_t)MROWS * CC];
__device__ float g_bufC[(size_t)MROWS * CC];
__device__ float g_biasNN[4 * NTOK * NTOK];

// ---------------------------------------------------------------------------
// f32x2 helpers (packed dual-FMA; doubles fp32 throughput on sm_103a)
// ---------------------------------------------------------------------------
__device__ __forceinline__ ull dupf(float x) {
    ull r;
    asm("mov.b64 %0, {%1, %1};" : "=l"(r) : "f"(x));
    return r;
}
__device__ __forceinline__ void ffma2(ull& d, ull a, ull b) {
    asm("fma.rn.f32x2 %0, %1, %2, %0;" : "+l"(d) : "l"(a), "l"(b));
}
__device__ __forceinline__ float f2lo(ull v) { return __uint_as_float((unsigned)v); }
__device__ __forceinline__ float f2hi(ull v) { return __uint_as_float((unsigned)(v >> 32)); }

// ---------------------------------------------------------------------------
// Relative-position-bias expansion
// ---------------------------------------------------------------------------
__global__ void bias_expand_kernel(const float* __restrict__ rpb) {
    int idx = blockIdx.x * blockDim.x + threadIdx.x;
    if (idx >= 4 * NTOK * NTOK) return;
    int h = idx / (NTOK * NTOK);
    int r = idx % (NTOK * NTOK);
    int i = r / NTOK, j = r % NTOK;
    int ti = i / 49, hi = (i / 7) % 7, wi = i % 7;
    int tj = j / 49, hj = (j / 7) % 7, wj = j % 7;
    int ridx = (ti - tj + 1) * 169 + (hi - hj + 6) * 13 + (wi - wj + 6);
    g_biasNN[idx] = rpb[ridx * 4 + h];
}

// ---------------------------------------------------------------------------
// LN1 + cyclic shift + window partition (one warp per row)
// ---------------------------------------------------------------------------
__global__ void ln_gather_kernel(const float* __restrict__ x,
                                 const float* __restrict__ g,
                                 const float* __restrict__ bta,
                                 float* __restrict__ out) {
    int warp = threadIdx.x >> 5, lane = threadIdx.x & 31;
    int row = blockIdx.x * 8 + warp;
    int bwin = row / NTOK, n = row % NTOK;
    int b = bwin >> 8, win = bwin & 255;
    int tw = win >> 6, hw = (win >> 3) & 7, ww = win & 7;
    int t0 = n / 49, r49 = n % 49, h0 = r49 / 7, w0 = r49 % 7;
    int tg = (tw * 2 + t0 + 1) & 7;
    int hg = hw * 7 + h0 + 3; if (hg >= 56) hg -= 56;
    int wg = ww * 7 + w0 + 3; if (wg >= 56) wg -= 56;
    const float* src = x + ((size_t)b * LTOK + (size_t)(tg * 56 + hg) * 56 + wg) * CC;

    float v[4]; float s = 0.f;
#pragma unroll
    for (int k = 0; k < 4; k++) { v[k] = src[lane + 32 * k]; s += v[k]; }
#pragma unroll
    for (int o = 16; o > 0; o >>= 1) s += __shfl_xor_sync(0xffffffffu, s, o);
    float mean = s * (1.0f / CC);
    float q = 0.f;
#pragma unroll
    for (int k = 0; k < 4; k++) { float d = v[k] - mean; q += d * d; }
#pragma unroll
    for (int o = 16; o > 0; o >>= 1) q += __shfl_xor_sync(0xffffffffu, q, o);
    float rstd = rsqrtf(q * (1.0f / CC) + EPS);
    float* dst = out + (size_t)row * CC;
#pragma unroll
    for (int k = 0; k < 4; k++) {
        int c = lane + 32 * k;
        dst[c] = (v[k] - mean) * rstd * g[c] + bta[c];
    }
}

// ---------------------------------------------------------------------------
// Plain LayerNorm
// ---------------------------------------------------------------------------
__global__ void ln_kernel(const float* __restrict__ in,
                          const float* __restrict__ g,
                          const float* __restrict__ bta,
                          float* __restrict__ out) {
    int warp = threadIdx.x >> 5, lane = threadIdx.x & 31;
    int row = blockIdx.x * 8 + warp;
    const float* src = in + (size_t)row * CC;
    float v[4]; float s = 0.f;
#pragma unroll
    for (int k = 0; k < 4; k++) { v[k] = src[lane + 32 * k]; s += v[k]; }
#pragma unroll
    for (int o = 16; o > 0; o >>= 1) s += __shfl_xor_sync(0xffffffffu, s, o);
    float mean = s * (1.0f / CC);
    float q = 0.f;
#pragma unroll
    for (int k = 0; k < 4; k++) { float d = v[k] - mean; q += d * d; }
#pragma unroll
    for (int o = 16; o > 0; o >>= 1) q += __shfl_xor_sync(0xffffffffu, q, o);
    float rstd = rsqrtf(q * (1.0f / CC) + EPS);
    float* dst = out + (size_t)row * CC;
#pragma unroll
    for (int k = 0; k < 4; k++) {
        int c = lane + 32 * k;
        dst[c] = (v[k] - mean) * rstd * g[c] + bta[c];
    }
}

// ---------------------------------------------------------------------------
// FFMA2 GEMM: out[M,N] = A[M,K] @ W[K,N] + bias (+epi)
// epi: 0 = bias, 1 = bias+GELU(exact), 2 = bias+resid
// 128x128 tile, BK=16, 256 threads, 8Mx8N micro via f32x2 m-pairs.
// Requires M%128==0, N%128==0, K%16==0.
// ---------------------------------------------------------------------------
__global__ __launch_bounds__(256) void gemm2_kernel(
        const float* __restrict__ A, const float* __restrict__ W,
        const float* __restrict__ bias, const float* __restrict__ resid,
        float* __restrict__ out, int M, int Np, int K, int epi) {
    __shared__ __align__(16) float As[16][128];   // As[kk][m]
    __shared__ __align__(16) float Ws[16][128];   // Ws[kk][n]

    int t = threadIdx.x;
    int tx = t & 15, ty = t >> 4;
    int n0 = blockIdx.x << 7, m0 = blockIdx.y << 7;

    ull acc[4][8];
#pragma unroll
    for (int i = 0; i < 4; i++)
#pragma unroll
        for (int j = 0; j < 8; j++) acc[i][j] = 0ull;

    int am = t >> 2;            // 0..63
    int ak = (t & 3) << 2;      // 0,4,8,12
    int wn = (t & 31) << 2;     // 0..124
    int wk = t >> 5;            // 0..7

    const float* Abase = A + (size_t)m0 * K;

    for (int kt = 0; kt < K; kt += 16) {
#pragma unroll
        for (int p = 0; p < 2; p++) {
            int m = am + p * 64;
            float4 av = *(const float4*)(Abase + (size_t)m * K + kt + ak);
            As[ak + 0][m] = av.x; As[ak + 1][m] = av.y;
            As[ak + 2][m] = av.z; As[ak + 3][m] = av.w;
        }
#pragma unroll
        for (int p = 0; p < 2; p++) {
            int kk = wk + p * 8;
            *(float4*)&Ws[kk][wn] = *(const float4*)(W + (size_t)(kt + kk) * Np + n0 + wn);
        }
        __syncthreads();
#pragma unroll
        for (int kk = 0; kk < 16; kk++) {
            ulonglong2 aA = *(const ulonglong2*)&As[kk][ty << 2];
            ulonglong2 aB = *(const ulonglong2*)&As[kk][64 + (ty << 2)];
            float4 b0 = *(const float4*)&Ws[kk][tx << 2];
            float4 b1 = *(const float4*)&Ws[kk][64 + (tx << 2)];
            ull bd[8];
            bd[0] = dupf(b0.x); bd[1] = dupf(b0.y); bd[2] = dupf(b0.z); bd[3] = dupf(b0.w);
            bd[4] = dupf(b1.x); bd[5] = dupf(b1.y); bd[6] = dupf(b1.z); bd[7] = dupf(b1.w);
#pragma unroll
            for (int j = 0; j < 8; j++) {
                ffma2(acc[0][j], aA.x, bd[j]);
                ffma2(acc[1][j], aA.y, bd[j]);
                ffma2(acc[2][j], aB.x, bd[j]);
                ffma2(acc[3][j], aB.y, bd[j]);
            }
        }
        __syncthreads();
    }

    float bs[8];
#pragma unroll
    for (int j = 0; j < 4; j++) {
        bs[j]     = bias[n0 + (tx << 2) + j];
        bs[4 + j] = bias[n0 + 64 + (tx << 2) + j];
    }
#pragma unroll
    for (int g = 0; g < 2; g++) {
#pragma unroll
        for (int rr = 0; rr < 4; rr++) {
            int m = m0 + g * 64 + (ty << 2) + rr;
            int mp = g * 2 + (rr >> 1);
            int hi = rr & 1;
            float v[8];
#pragma unroll
            for (int j = 0; j < 8; j++) {
                float f = hi ? f2hi(acc[mp][j]) : f2lo(acc[mp][j]);
                f += bs[j];
                if (epi == 1) f = 0.5f * f * (1.0f + erff(f * 0.7071067811865475f));
                v[j] = f;
            }
            size_t ro = (size_t)m * Np;
            if (epi == 2) {
#pragma unroll
                for (int j = 0; j < 4; j++) {
                    v[j]     += resid[ro + n0 + (tx << 2) + j];
                    v[4 + j] += resid[ro + n0 + 64 + (tx << 2) + j];
                }
            }
            *(float4*)&out[ro + n0 + (tx << 2)]      = make_float4(v[0], v[1], v[2], v[3]);
            *(float4*)&out[ro + n0 + 64 + (tx << 2)] = make_float4(v[4], v[5], v[6], v[7]);
        }
    }
}

// ---------------------------------------------------------------------------
// Attention: one CTA per (window, head). 256 threads, f32x2 math,
// warp-parallel softmax.
// ---------------------------------------------------------------------------
#define APAD 34
#define ATTN_SMEM_FLOATS (3 * 98 * APAD + 98 * 98)

__global__ __launch_bounds__(256) void attn_kernel(const float* __restrict__ qkv,
                                                   float* __restrict__ out) {
    extern __shared__ float sm[];
    float* sq = sm;
    float* sk = sm + 98 * APAD;
    float* sv = sm + 2 * 98 * APAD;
    float* ss = sm + 3 * 98 * APAD;
    __shared__ int sreg[98];

    int bwin = blockIdx.x >> 2;
    int head = blockIdx.x & 3;
    int tid = threadIdx.x;

    size_t base = (size_t)bwin * NTOK * 384 + head * 32;
    for (int idx = tid; idx < 98 * 32; idx += 256) {
        int n = idx >> 5, d = idx & 31;
        size_t o = base + (size_t)n * 384 + d;
        sq[n * APAD + d] = qkv[o] * SCALE;
        sk[n * APAD + d] = qkv[o + 128];
        sv[n * APAD + d] = qkv[o + 256];
    }
    if (tid < 98) {
        int win = bwin & 255;
        int tw = win >> 6, hw = (win >> 3) & 7, ww = win & 7;
        int t0 = tid / 49, r = tid % 49, h0 = r / 7, w0 = r % 7;
        int tg = tw * 2 + t0, hg = hw * 7 + h0, wg = ww * 7 + w0;
        int rt = tg < 6 ? 0 : (tg < 7 ? 1 : 2);
        int rh = hg < 49 ? 0 : (hg < 53 ? 1 : 2);
        int rw = wg < 49 ? 0 : (wg < 53 ? 1 : 2);
        sreg[tid] = rt * 9 + rh * 3 + rw;
    }
    __syncthreads();

    // S = q k^T + bias + mask  (f32x2 along reduction, 7 cols per item)
    const float* bh = g_biasNN + head * (NTOK * NTOK);
    for (int idx = tid; idx < 98 * 14; idx += 256) {
        int i = idx / 14, jg = idx % 14;
        int j0 = jg * 7;
        ull acc2[7];
#pragma unroll
        for (int u = 0; u < 7; u++) acc2[u] = 0ull;
        const ull* qp = (const ull*)(sq + i * APAD);
#pragma unroll
        for (int kk = 0; kk < 16; kk++) {
            ull qa = qp[kk];
#pragma unroll
            for (int u = 0; u < 7; u++)
                ffma2(acc2[u], qa, *(const ull*)(sk + (j0 + u) * APAD + kk * 2));
        }
        int ri = sreg[i];
#pragma unroll
        for (int u = 0; u < 7; u++) {
            int j = j0 + u;
            float s = f2lo(acc2[u]) + f2hi(acc2[u]);
            float mval = (ri != sreg[j]) ? -100.0f : 0.0f;
            ss[i * 98 + j] = s + bh[i * 98 + j] + mval;
        }
    }
    __syncthreads();

    // softmax: one warp per row
    {
        int warp = tid >> 5, lane = tid & 31;
        for (int row = warp; row < 98; row += 8) {
            float* r = ss + row * 98;
            float mx = -1e30f;
            for (int j = lane; j < 98; j += 32) mx = fmaxf(mx, r[j]);
#pragma unroll
            for (int o = 16; o > 0; o >>= 1) mx = fmaxf(mx, __shfl_xor_sync(0xffffffffu, mx, o));
            float sum = 0.f;
            for (int j = lane; j < 98; j += 32) { float e = __expf(r[j] - mx); r[j] = e; sum += e; }
#pragma unroll
            for (int o = 16; o > 0; o >>= 1) sum += __shfl_xor_sync(0xffffffffu, sum, o);
            float inv = 1.0f / sum;
            for (int j = lane; j < 98; j += 32) r[j] *= inv;
        }
    }
    __syncthreads();

    // O = P @ V  (f32x2 along head-dim, 8 dims per item)
    size_t obase = (size_t)bwin * NTOK * CC + head * 32;
    for (int idx = tid; idx < 98 * 4; idx += 256) {
        int i = idx >> 2, d0 = (idx & 3) << 3;
        ull acc2[4] = {0ull, 0ull, 0ull, 0ull};
        const float* pr = ss + i * 98;
        for (int m = 0; m < 98; m++) {
            ull pd = dupf(pr[m]);
            const ull* vp = (const ull*)(sv + m * APAD + d0);
            ffma2(acc2[0], pd, vp[0]);
            ffma2(acc2[1], pd, vp[1]);
            ffma2(acc2[2], pd, vp[2]);
            ffma2(acc2[3], pd, vp[3]);
        }
        float* op = out + obase + (size_t)i * CC + d0;
#pragma unroll
        for (int e = 0; e < 4; e++) {
            op[2 * e]     = f2lo(acc2[e]);
            op[2 * e + 1] = f2hi(acc2[e]);
        }
    }
}

// ---------------------------------------------------------------------------
// window_reverse + roll(+SS) + shortcut add
// ---------------------------------------------------------------------------
__global__ void scatter_resid_kernel(const float* __restrict__ x,
                                     const float* __restrict__ projout,
                                     float* __restrict__ out) {
    int warp = threadIdx.x >> 5, lane = threadIdx.x & 31;
    int row = blockIdx.x * 8 + warp;
    int b = row / LTOK, l = row % LTOK;
    int tg = l / 3136, rem = l % 3136;
    int hg = rem / 56, wg = rem % 56;
    int tp = (tg + 7) & 7;
    int hp = hg - 3; if (hp < 0) hp += 56;
    int wp = wg - 3; if (wp < 0) wp += 56;
    int win = (tp >> 1) * 64 + (hp / 7) * 8 + (wp / 7);
    int n = (tp & 1) * 49 + (hp % 7) * 7 + (wp % 7);
    const float* src = projout + ((size_t)(b * NWIN + win) * NTOK + n) * CC;
    const float* xr = x + (size_t)row * CC;
    float* dst = out + (size_t)row * CC;
#pragma unroll
    for (int k = 0; k < 4; k++) {
        int c = lane + 32 * k;
        dst[c] = xr[c] + src[c];
    }
}

// ---------------------------------------------------------------------------
// Launch
// ---------------------------------------------------------------------------
extern "C" void kernel_launch(void* const* d_in, const int* in_sizes, int n_in,
                              void* d_out, int out_size) {
    const float* x       = (const float*)d_in[0];
    const float* norm1_g = (const float*)d_in[1];
    const float* norm1_b = (const float*)d_in[2];
    const float* qkv_w   = (const float*)d_in[3];
    const float* qkv_b   = (const float*)d_in[4];
    const float* proj_w  = (const float*)d_in[5];
    const float* proj_b  = (const float*)d_in[6];
    const float* rpb     = (const float*)d_in[7];
    const float* norm2_g = (const float*)d_in[8];
    const float* norm2_b = (const float*)d_in[9];
    const float* fc1_w   = (const float*)d_in[10];
    const float* fc1_b   = (const float*)d_in[11];
    const float* fc2_w   = (const float*)d_in[12];
    const float* fc2_b   = (const float*)d_in[13];
    float* outp = (float*)d_out;

    float *bufA, *bufB, *bufC;
    cudaGetSymbolAddress((void**)&bufA, g_bufA);
    cudaGetSymbolAddress((void**)&bufB, g_bufB);
    cudaGetSymbolAddress((void**)&bufC, g_bufC);

    cudaFuncSetAttribute(attn_kernel, cudaFuncAttributeMaxDynamicSharedMemorySize,
                         ATTN_SMEM_FLOATS * sizeof(float));

    // 1. bias expansion
    bias_expand_kernel<<<(4 * NTOK * NTOK + 255) / 256, 256>>>(rpb);

    // 2. LN1 + shift + partition -> bufB
    ln_gather_kernel<<<MROWS / 8, 256>>>(x, norm1_g, norm1_b, bufB);

    // 3. QKV GEMM -> bufA [MROWS, 384]
    {
        dim3 grid(384 / 128, MROWS / 128);
        gemm2_kernel<<<grid, 256>>>(bufB, qkv_w, qkv_b, nullptr, bufA,
                                    MROWS, 384, 128, 0);
    }

    // 4. attention -> bufB
    attn_kernel<<<BWIN * 4, 256, ATTN_SMEM_FLOATS * sizeof(float)>>>(bufA, bufB);

    // 5. proj GEMM -> bufC
    {
        dim3 grid(1, MROWS / 128);
        gemm2_kernel<<<grid, 256>>>(bufB, proj_w, proj_b, nullptr, bufC,
                                    MROWS, 128, 128, 0);
    }

    // 6. window reverse + roll + shortcut -> bufB = x2
    scatter_resid_kernel<<<MROWS / 8, 256>>>(x, bufC, bufB);

    // 7. LN2 -> bufC
    ln_kernel<<<MROWS / 8, 256>>>(bufB, norm2_g, norm2_b, bufC);

    // 8. FC1 + GELU -> bufA [MROWS, 512]
    {
        dim3 grid(512 / 128, MROWS / 128);
        gemm2_kernel<<<grid, 256>>>(bufC, fc1_w, fc1_b, nullptr, bufA,
                                    MROWS, 512, 128, 1);
    }

    // 9. FC2 + residual -> d_out
    {
        dim3 grid(1, MROWS / 128);
        gemm2_kernel<<<grid, 256>>>(bufA, fc2_w, fc2_b, bufB, outp,
                                    MROWS, 128, 512, 2);
    }
}

// round 4
// speedup vs baseline: 2.4642x; 1.8561x over previous
#include <cuda_runtime.h>
#include <cuda_bf16.h>
#include <math.h>
#include <stdint.h>

// ---------------------------------------------------------------------------
// Problem constants
// ---------------------------------------------------------------------------
#define CC 128
#define NTOK 98
#define BWIN 2048
#define LTOK 25088
#define MROWS 200704
#define HID 512
#define SCALE 0.17677669529663687f
#define EPS 1e-5f

typedef unsigned long long ull;

// ---------------------------------------------------------------------------
// Scratch
// ---------------------------------------------------------------------------
__device__ __nv_bfloat16 g_bh1[(size_t)MROWS * HID];  // qkv out (384) / fc1 out (512)
__device__ __nv_bfloat16 g_bh2[(size_t)MROWS * CC];   // ln1 out / attn out / ln2 out
__device__ float g_bufB[(size_t)MROWS * CC];          // x2 residual
__device__ float g_bufC[(size_t)MROWS * CC];          // proj out
__device__ float g_biasNN[4 * NTOK * NTOK];
__device__ __nv_bfloat16 g_wt[196608];                // transposed bf16 weights [N][K]

#define WT_QKV 0        // 384 x 128
#define WT_PROJ 49152   // 128 x 128
#define WT_FC1 65536    // 512 x 128
#define WT_FC2 131072   // 128 x 512

// ---------------------------------------------------------------------------
// f32x2 helpers
// ---------------------------------------------------------------------------
__device__ __forceinline__ ull dupf(float x) {
    ull r; asm("mov.b64 %0, {%1, %1};" : "=l"(r) : "f"(x)); return r;
}
__device__ __forceinline__ void ffma2(ull& d, ull a, ull b) {
    asm("fma.rn.f32x2 %0, %1, %2, %0;" : "+l"(d) : "l"(a), "l"(b));
}
__device__ __forceinline__ float f2lo(ull v) { return __uint_as_float((unsigned)v); }
__device__ __forceinline__ float f2hi(ull v) { return __uint_as_float((unsigned)(v >> 32)); }

// ---------------------------------------------------------------------------
// HMMA helper: m16n8k16 row.col f32.bf16.bf16.f32 (baseline PTX, sm_80+)
// ---------------------------------------------------------------------------
__device__ __forceinline__ void mma16816(float* c, const uint32_t* a, const uint32_t* b) {
    asm volatile(
        "mma.sync.aligned.m16n8k16.row.col.f32.bf16.bf16.f32 "
        "{%0,%1,%2,%3}, {%4,%5,%6,%7}, {%8,%9}, {%0,%1,%2,%3};"
        : "+f"(c[0]), "+f"(c[1]), "+f"(c[2]), "+f"(c[3])
        : "r"(a[0]), "r"(a[1]), "r"(a[2]), "r"(a[3]), "r"(b[0]), "r"(b[1]));
}

// ---------------------------------------------------------------------------
// Weight prep: fp32 [K,N] -> bf16 transposed [N,K]
// ---------------------------------------------------------------------------
__global__ void wprep_kernel(const float* __restrict__ W,
                             __nv_bfloat16* __restrict__ dst, int K, int N) {
    int idx = blockIdx.x * blockDim.x + threadIdx.x;
    if (idx >= K * N) return;
    int k = idx / N, n = idx % N;
    dst[(size_t)n * K + k] = __float2bfloat16(W[idx]);
}

// ---------------------------------------------------------------------------
// Relative-position-bias expansion
// ---------------------------------------------------------------------------
__global__ void bias_expand_kernel(const float* __restrict__ rpb) {
    int idx = blockIdx.x * blockDim.x + threadIdx.x;
    if (idx >= 4 * NTOK * NTOK) return;
    int h = idx / (NTOK * NTOK);
    int r = idx % (NTOK * NTOK);
    int i = r / NTOK, j = r % NTOK;
    int ti = i / 49, hi = (i / 7) % 7, wi = i % 7;
    int tj = j / 49, hj = (j / 7) % 7, wj = j % 7;
    int ridx = (ti - tj + 1) * 169 + (hi - hj + 6) * 13 + (wi - wj + 6);
    g_biasNN[idx] = rpb[ridx * 4 + h];
}

// ---------------------------------------------------------------------------
// LN1 + shift + window partition -> bf16
// ---------------------------------------------------------------------------
__global__ void ln_gather_kernel(const float* __restrict__ x,
                                 const float* __restrict__ g,
                                 const float* __restrict__ bta,
                                 __nv_bfloat16* __restrict__ out) {
    int warp = threadIdx.x >> 5, lane = threadIdx.x & 31;
    int row = blockIdx.x * 8 + warp;
    int bwin = row / NTOK, n = row % NTOK;
    int b = bwin >> 8, win = bwin & 255;
    int tw = win >> 6, hw = (win >> 3) & 7, ww = win & 7;
    int t0 = n / 49, r49 = n % 49, h0 = r49 / 7, w0 = r49 % 7;
    int tg = (tw * 2 + t0 + 1) & 7;
    int hg = hw * 7 + h0 + 3; if (hg >= 56) hg -= 56;
    int wg = ww * 7 + w0 + 3; if (wg >= 56) wg -= 56;
    const float* src = x + ((size_t)b * LTOK + (size_t)(tg * 56 + hg) * 56 + wg) * CC;

    float v[4]; float s = 0.f;
#pragma unroll
    for (int k = 0; k < 4; k++) { v[k] = src[lane + 32 * k]; s += v[k]; }
#pragma unroll
    for (int o = 16; o > 0; o >>= 1) s += __shfl_xor_sync(0xffffffffu, s, o);
    float mean = s * (1.0f / CC);
    float q = 0.f;
#pragma unroll
    for (int k = 0; k < 4; k++) { float d = v[k] - mean; q += d * d; }
#pragma unroll
    for (int o = 16; o > 0; o >>= 1) q += __shfl_xor_sync(0xffffffffu, q, o);
    float rstd = rsqrtf(q * (1.0f / CC) + EPS);
    __nv_bfloat16* dst = out + (size_t)row * CC;
#pragma unroll
    for (int k = 0; k < 4; k++) {
        int c = lane + 32 * k;
        dst[c] = __float2bfloat16((v[k] - mean) * rstd * g[c] + bta[c]);
    }
}

// ---------------------------------------------------------------------------
// LN2 (fp32 in -> bf16 out)
// ---------------------------------------------------------------------------
__global__ void ln_kernel(const float* __restrict__ in,
                          const float* __restrict__ g,
                          const float* __restrict__ bta,
                          __nv_bfloat16* __restrict__ out) {
    int warp = threadIdx.x >> 5, lane = threadIdx.x & 31;
    int row = blockIdx.x * 8 + warp;
    const float* src = in + (size_t)row * CC;
    float v[4]; float s = 0.f;
#pragma unroll
    for (int k = 0; k < 4; k++) { v[k] = src[lane + 32 * k]; s += v[k]; }
#pragma unroll
    for (int o = 16; o > 0; o >>= 1) s += __shfl_xor_sync(0xffffffffu, s, o);
    float mean = s * (1.0f / CC);
    float q = 0.f;
#pragma unroll
    for (int k = 0; k < 4; k++) { float d = v[k] - mean; q += d * d; }
#pragma unroll
    for (int o = 16; o > 0; o >>= 1) q += __shfl_xor_sync(0xffffffffu, q, o);
    float rstd = rsqrtf(q * (1.0f / CC) + EPS);
    __nv_bfloat16* dst = out + (size_t)row * CC;
#pragma unroll
    for (int k = 0; k < 4; k++) {
        int c = lane + 32 * k;
        dst[c] = __float2bfloat16((v[k] - mean) * rstd * g[c] + bta[c]);
    }
}

// ---------------------------------------------------------------------------
// HMMA GEMM: out[M,N] = A[M,K] @ W + bias (+epi)
// A bf16 row-major [M,K], Wt bf16 transposed [N,K].
// CTA 128x128, BK=32, 8 warps (2m x 4n), warp tile 64x32.
// epi: 0 bias, 1 bias+GELU, 2 bias+resid. out_bf16 selects output dtype.
// ---------------------------------------------------------------------------
#define SSTR 40   // smem row stride in bf16 elems (conflict-free, 16B aligned)

__global__ __launch_bounds__(256) void gemm_mma_kernel(
        const __nv_bfloat16* __restrict__ A, const __nv_bfloat16* __restrict__ Wt,
        const float* __restrict__ bias, const float* __restrict__ resid,
        void* __restrict__ outv, int M, int Np, int K, int epi, int out_bf16) {
    __shared__ __align__(16) __nv_bfloat16 sA[128 * SSTR];
    __shared__ __align__(16) __nv_bfloat16 sB[128 * SSTR];

    int t = threadIdx.x;
    int warp = t >> 5, lane = t & 31;
    int wm = warp & 1, wn = warp >> 1;
    int gid = lane >> 2, tig = lane & 3;
    int n0 = blockIdx.x << 7, m0 = blockIdx.y << 7;

    float acc[4][4][4];
#pragma unroll
    for (int mt = 0; mt < 4; mt++)
#pragma unroll
        for (int nt = 0; nt < 4; nt++)
#pragma unroll
            for (int e = 0; e < 4; e++) acc[mt][nt][e] = 0.f;

    int lr = t >> 2;               // 0..63
    int lc = (t & 3) << 3;         // 0,8,16,24

    const __nv_bfloat16* Ag = A + (size_t)(m0 + lr) * K + lc;
    const __nv_bfloat16* Bg = Wt + (size_t)(n0 + lr) * K + lc;

    int nk = K >> 5;
    float4 pa0 = *(const float4*)Ag;
    float4 pa1 = *(const float4*)(Ag + (size_t)64 * K);
    float4 pb0 = *(const float4*)Bg;
    float4 pb1 = *(const float4*)(Bg + (size_t)64 * K);

    for (int kc = 0; kc < nk; kc++) {
        *(float4*)&sA[lr * SSTR + lc] = pa0;
        *(float4*)&sA[(lr + 64) * SSTR + lc] = pa1;
        *(float4*)&sB[lr * SSTR + lc] = pb0;
        *(float4*)&sB[(lr + 64) * SSTR + lc] = pb1;
        __syncthreads();
        if (kc + 1 < nk) {
            int kt = (kc + 1) << 5;
            pa0 = *(const float4*)(Ag + kt);
            pa1 = *(const float4*)(Ag + (size_t)64 * K + kt);
            pb0 = *(const float4*)(Bg + kt);
            pb1 = *(const float4*)(Bg + (size_t)64 * K + kt);
        }
#pragma unroll
        for (int ks = 0; ks < 2; ks++) {
            int k0 = ks << 4;
            uint32_t af[4][4], bf[4][2];
#pragma unroll
            for (int mt = 0; mt < 4; mt++) {
                int base = (wm * 64 + mt * 16 + gid) * SSTR + k0 + tig * 2;
                af[mt][0] = *(const uint32_t*)&sA[base];
                af[mt][1] = *(const uint32_t*)&sA[base + 8 * SSTR];
                af[mt][2] = *(const uint32_t*)&sA[base + 8];
                af[mt][3] = *(const uint32_t*)&sA[base + 8 * SSTR + 8];
            }
#pragma unroll
            for (int nt = 0; nt < 4; nt++) {
                int base = (wn * 32 + nt * 8 + gid) * SSTR + k0 + tig * 2;
                bf[nt][0] = *(const uint32_t*)&sB[base];
                bf[nt][1] = *(const uint32_t*)&sB[base + 8];
            }
#pragma unroll
            for (int mt = 0; mt < 4; mt++)
#pragma unroll
                for (int nt = 0; nt < 4; nt++)
                    mma16816(acc[mt][nt], af[mt], bf[nt]);
        }
        __syncthreads();
    }

    // epilogue
#pragma unroll
    for (int mt = 0; mt < 4; mt++) {
        int row = m0 + wm * 64 + mt * 16 + gid;
#pragma unroll
        for (int nt = 0; nt < 4; nt++) {
            int col = n0 + wn * 32 + nt * 8 + tig * 2;
            float b0 = bias[col], b1 = bias[col + 1];
            float v00 = acc[mt][nt][0] + b0, v01 = acc[mt][nt][1] + b1;
            float v10 = acc[mt][nt][2] + b0, v11 = acc[mt][nt][3] + b1;
            if (epi == 1) {
                v00 = 0.5f * v00 * (1.0f + erff(v00 * 0.7071067811865475f));
                v01 = 0.5f * v01 * (1.0f + erff(v01 * 0.7071067811865475f));
                v10 = 0.5f * v10 * (1.0f + erff(v10 * 0.7071067811865475f));
                v11 = 0.5f * v11 * (1.0f + erff(v11 * 0.7071067811865475f));
            }
            size_t o0 = (size_t)row * Np + col;
            size_t o1 = (size_t)(row + 8) * Np + col;
            if (epi == 2) {
                float2 r0 = *(const float2*)(resid + o0);
                float2 r1 = *(const float2*)(resid + o1);
                v00 += r0.x; v01 += r0.y; v10 += r1.x; v11 += r1.y;
            }
            if (out_bf16) {
                __nv_bfloat16* op = (__nv_bfloat16*)outv;
                *(__nv_bfloat162*)(op + o0) = __floats2bfloat162_rn(v00, v01);
                *(__nv_bfloat162*)(op + o1) = __floats2bfloat162_rn(v10, v11);
            } else {
                float* op = (float*)outv;
                *(float2*)(op + o0) = make_float2(v00, v01);
                *(float2*)(op + o1) = make_float2(v10, v11);
            }
        }
    }
}

// ---------------------------------------------------------------------------
// Attention: one CTA per (window, head). 256 threads, bf16 in/out,
// 2-row register blocking, f32x2 math, warp-parallel softmax.
// ---------------------------------------------------------------------------
#define APAD 34
#define ATTN_SMEM_FLOATS (3 * 98 * APAD + 98 * 98)

__global__ __launch_bounds__(256) void attn_kernel(const __nv_bfloat16* __restrict__ qkv,
                                                   __nv_bfloat16* __restrict__ out) {
    extern __shared__ float sm[];
    float* sq = sm;
    float* sk = sm + 98 * APAD;
    float* sv = sm + 2 * 98 * APAD;
    float* ss = sm + 3 * 98 * APAD;
    __shared__ int sreg[98];

    int bwin = blockIdx.x >> 2;
    int head = blockIdx.x & 3;
    int tid = threadIdx.x;

    size_t base = (size_t)bwin * NTOK * 384 + head * 32;
    for (int idx = tid; idx < 98 * 16; idx += 256) {
        int n = idx >> 4, d2 = (idx & 15) << 1;
        size_t o = base + (size_t)n * 384 + d2;
        float2 q2 = __bfloat1622float2(*(const __nv_bfloat162*)(qkv + o));
        float2 k2 = __bfloat1622float2(*(const __nv_bfloat162*)(qkv + o + 128));
        float2 v2 = __bfloat1622float2(*(const __nv_bfloat162*)(qkv + o + 256));
        sq[n * APAD + d2] = q2.x * SCALE; sq[n * APAD + d2 + 1] = q2.y * SCALE;
        sk[n * APAD + d2] = k2.x;         sk[n * APAD + d2 + 1] = k2.y;
        sv[n * APAD + d2] = v2.x;         sv[n * APAD + d2 + 1] = v2.y;
    }
    if (tid < 98) {
        int win = bwin & 255;
        int tw = win >> 6, hw = (win >> 3) & 7, ww = win & 7;
        int t0 = tid / 49, r = tid % 49, h0 = r / 7, w0 = r % 7;
        int tg = tw * 2 + t0, hg = hw * 7 + h0, wg = ww * 7 + w0;
        int rt = tg < 6 ? 0 : (tg < 7 ? 1 : 2);
        int rh = hg < 49 ? 0 : (hg < 53 ? 1 : 2);
        int rw = wg < 49 ? 0 : (wg < 53 ? 1 : 2);
        sreg[tid] = rt * 9 + rh * 3 + rw;
    }
    __syncthreads();

    // S = q k^T + bias + mask: 49 i-pairs x 14 j-groups
    const float* bh = g_biasNN + head * (NTOK * NTOK);
    for (int idx = tid; idx < 49 * 14; idx += 256) {
        int ip = idx / 14, jg = idx % 14;
        int i0 = ip * 2, j0 = jg * 7;
        ull a0[7], a1[7];
#pragma unroll
        for (int u = 0; u < 7; u++) { a0[u] = 0ull; a1[u] = 0ull; }
        const ull* q0 = (const ull*)(sq + i0 * APAD);
        const ull* q1 = (const ull*)(sq + (i0 + 1) * APAD);
#pragma unroll
        for (int kk = 0; kk < 16; kk++) {
            ull qa = q0[kk], qb = q1[kk];
#pragma unroll
            for (int u = 0; u < 7; u++) {
                ull kv = *(const ull*)(sk + (j0 + u) * APAD + kk * 2);
                ffma2(a0[u], qa, kv);
                ffma2(a1[u], qb, kv);
            }
        }
        int r0 = sreg[i0], r1 = sreg[i0 + 1];
#pragma unroll
        for (int u = 0; u < 7; u++) {
            int j = j0 + u;
            int rj = sreg[j];
            ss[i0 * 98 + j] = f2lo(a0[u]) + f2hi(a0[u]) + bh[i0 * 98 + j]
                              + (r0 != rj ? -100.0f : 0.0f);
            ss[(i0 + 1) * 98 + j] = f2lo(a1[u]) + f2hi(a1[u]) + bh[(i0 + 1) * 98 + j]
                              + (r1 != rj ? -100.0f : 0.0f);
        }
    }
    __syncthreads();

    // softmax: one warp per row
    {
        int warp = tid >> 5, lane = tid & 31;
        for (int row = warp; row < 98; row += 8) {
            float* r = ss + row * 98;
            float mx = -1e30f;
            for (int j = lane; j < 98; j += 32) mx = fmaxf(mx, r[j]);
#pragma unroll
            for (int o = 16; o > 0; o >>= 1) mx = fmaxf(mx, __shfl_xor_sync(0xffffffffu, mx, o));
            float sum = 0.f;
            for (int j = lane; j < 98; j += 32) { float e = __expf(r[j] - mx); r[j] = e; sum += e; }
#pragma unroll
            for (int o = 16; o > 0; o >>= 1) sum += __shfl_xor_sync(0xffffffffu, sum, o);
            float inv = 1.0f / sum;
            for (int j = lane; j < 98; j += 32) r[j] *= inv;
        }
    }
    __syncthreads();

    // O = P @ V: 49 i-pairs x 4 d-groups of 8
    size_t obase = (size_t)bwin * NTOK * CC + head * 32;
    for (int idx = tid; idx < 49 * 4; idx += 256) {
        int ip = idx >> 2, d0 = (idx & 3) << 3;
        int i0 = ip * 2;
        ull a0[4] = {0ull, 0ull, 0ull, 0ull};
        ull a1[4] = {0ull, 0ull, 0ull, 0ull};
        const float* p0 = ss + i0 * 98;
        const float* p1 = p0 + 98;
        for (int m = 0; m < 98; m++) {
            ull pd0 = dupf(p0[m]);
            ull pd1 = dupf(p1[m]);
            const ull* vp = (const ull*)(sv + m * APAD + d0);
#pragma unroll
            for (int e = 0; e < 4; e++) {
                ull vv = vp[e];
                ffma2(a0[e], pd0, vv);
                ffma2(a1[e], pd1, vv);
            }
        }
        __nv_bfloat162* o0 = (__nv_bfloat162*)(out + obase + (size_t)i0 * CC + d0);
        __nv_bfloat162* o1 = (__nv_bfloat162*)(out + obase + (size_t)(i0 + 1) * CC + d0);
#pragma unroll
        for (int e = 0; e < 4; e++) {
            o0[e] = __floats2bfloat162_rn(f2lo(a0[e]), f2hi(a0[e]));
            o1[e] = __floats2bfloat162_rn(f2lo(a1[e]), f2hi(a1[e]));
        }
    }
}

// ---------------------------------------------------------------------------
// window_reverse + roll(+SS) + shortcut add (fp32)
// ---------------------------------------------------------------------------
__global__ void scatter_resid_kernel(const float* __restrict__ x,
                                     const float* __restrict__ projout,
                                     float* __restrict__ out) {
    int warp = threadIdx.x >> 5, lane = threadIdx.x & 31;
    int row = blockIdx.x * 8 + warp;
    int b = row / LTOK, l = row % LTOK;
    int tg = l / 3136, rem = l % 3136;
    int hg = rem / 56, wg = rem % 56;
    int tp = (tg + 7) & 7;
    int hp = hg - 3; if (hp < 0) hp += 56;
    int wp = wg - 3; if (wp < 0) wp += 56;
    int win = (tp >> 1) * 64 + (hp / 7) * 8 + (wp / 7);
    int n = (tp & 1) * 49 + (hp % 7) * 7 + (wp % 7);
    const float* src = projout + ((size_t)(b * 256 + win) * NTOK + n) * CC;
    const float* xr = x + (size_t)row * CC;
    float* dst = out + (size_t)row * CC;
#pragma unroll
    for (int k = 0; k < 4; k++) {
        int c = lane + 32 * k;
        dst[c] = xr[c] + src[c];
    }
}

// ---------------------------------------------------------------------------
// Launch
// ---------------------------------------------------------------------------
extern "C" void kernel_launch(void* const* d_in, const int* in_sizes, int n_in,
                              void* d_out, int out_size) {
    const float* x       = (const float*)d_in[0];
    const float* norm1_g = (const float*)d_in[1];
    const float* norm1_b = (const float*)d_in[2];
    const float* qkv_w   = (const float*)d_in[3];
    const float* qkv_b   = (const float*)d_in[4];
    const float* proj_w  = (const float*)d_in[5];
    const float* proj_b  = (const float*)d_in[6];
    const float* rpb     = (const float*)d_in[7];
    const float* norm2_g = (const float*)d_in[8];
    const float* norm2_b = (const float*)d_in[9];
    const float* fc1_w   = (const float*)d_in[10];
    const float* fc1_b   = (const float*)d_in[11];
    const float* fc2_w   = (const float*)d_in[12];
    const float* fc2_b   = (const float*)d_in[13];
    float* outp = (float*)d_out;

    __nv_bfloat16 *bh1, *bh2, *wt;
    float *bufB, *bufC;
    cudaGetSymbolAddress((void**)&bh1, g_bh1);
    cudaGetSymbolAddress((void**)&bh2, g_bh2);
    cudaGetSymbolAddress((void**)&wt, g_wt);
    cudaGetSymbolAddress((void**)&bufB, g_bufB);
    cudaGetSymbolAddress((void**)&bufC, g_bufC);

    cudaFuncSetAttribute(attn_kernel, cudaFuncAttributeMaxDynamicSharedMemorySize,
                         ATTN_SMEM_FLOATS * sizeof(float));

    // weight prep + bias expansion
    wprep_kernel<<<(128 * 384 + 255) / 256, 256>>>(qkv_w, wt + WT_QKV, 128, 384);
    wprep_kernel<<<(128 * 128 + 255) / 256, 256>>>(proj_w, wt + WT_PROJ, 128, 128);
    wprep_kernel<<<(128 * 512 + 255) / 256, 256>>>(fc1_w, wt + WT_FC1, 128, 512);
    wprep_kernel<<<(512 * 128 + 255) / 256, 256>>>(fc2_w, wt + WT_FC2, 512, 128);
    bias_expand_kernel<<<(4 * NTOK * NTOK + 255) / 256, 256>>>(rpb);

    // LN1 + shift + partition -> bh2 (bf16)
    ln_gather_kernel<<<MROWS / 8, 256>>>(x, norm1_g, norm1_b, bh2);

    // QKV GEMM -> bh1 bf16 [M,384]
    {
        dim3 grid(3, MROWS / 128);
        gemm_mma_kernel<<<grid, 256>>>(bh2, wt + WT_QKV, qkv_b, nullptr,
                                       bh1, MROWS, 384, 128, 0, 1);
    }

    // attention -> bh2 bf16
    attn_kernel<<<BWIN * 4, 256, ATTN_SMEM_FLOATS * sizeof(float)>>>(bh1, bh2);

    // proj GEMM -> bufC fp32
    {
        dim3 grid(1, MROWS / 128);
        gemm_mma_kernel<<<grid, 256>>>(bh2, wt + WT_PROJ, proj_b, nullptr,
                                       bufC, MROWS, 128, 128, 0, 0);
    }

    // window reverse + roll + shortcut -> bufB = x2 (fp32)
    scatter_resid_kernel<<<MROWS / 8, 256>>>(x, bufC, bufB);

    // LN2 -> bh2 bf16
    ln_kernel<<<MROWS / 8, 256>>>(bufB, norm2_g, norm2_b, bh2);

    // FC1 + GELU -> bh1 bf16 [M,512]
    {
        dim3 grid(4, MROWS / 128);
        gemm_mma_kernel<<<grid, 256>>>(bh2, wt + WT_FC1, fc1_b, nullptr,
                                       bh1, MROWS, 512, 128, 1, 1);
    }

    // FC2 + residual -> d_out fp32
    {
        dim3 grid(1, MROWS / 128);
        gemm_mma_kernel<<<grid, 256>>>(bh1, wt + WT_FC2, fc2_b, bufB,
                                       outp, MROWS, 128, 512, 2, 0);
    }
}

// round 5
// speedup vs baseline: 3.3732x; 1.3689x over previous
#include <cuda_runtime.h>
#include <cuda_bf16.h>
#include <math.h>
#include <stdint.h>

// ---------------------------------------------------------------------------
// Problem constants
// ---------------------------------------------------------------------------
#define CC 128
#define NTOK 98
#define BWIN 2048
#define LTOK 25088
#define MROWS 200704
#define HID 512
#define SCALE 0.17677669529663687f
#define EPS 1e-5f

typedef unsigned long long ull;

// ---------------------------------------------------------------------------
// Scratch
// ---------------------------------------------------------------------------
__device__ __nv_bfloat16 g_bh1[(size_t)MROWS * HID];  // qkv out (384) / fc1 out (512)
__device__ __nv_bfloat16 g_bh2[(size_t)MROWS * CC];   // ln1 out / attn out / ln2 out
__device__ float g_bufB[(size_t)MROWS * CC];          // x2 residual
__device__ float g_bufC[(size_t)MROWS * CC];          // proj out
__device__ float g_biasNN[4 * 112 * 112];             // padded rel-pos bias
__device__ __nv_bfloat16 g_wt[196608];                // transposed bf16 weights [N][K]

#define WT_QKV 0        // 384 x 128
#define WT_PROJ 49152   // 128 x 128
#define WT_FC1 65536    // 512 x 128
#define WT_FC2 131072   // 128 x 512

// ---------------------------------------------------------------------------
// HMMA helper: m16n8k16 row.col f32.bf16.bf16.f32 (baseline PTX, sm_80+)
// ---------------------------------------------------------------------------
__device__ __forceinline__ void mma16816(float* c, const uint32_t* a, const uint32_t* b) {
    asm volatile(
        "mma.sync.aligned.m16n8k16.row.col.f32.bf16.bf16.f32 "
        "{%0,%1,%2,%3}, {%4,%5,%6,%7}, {%8,%9}, {%0,%1,%2,%3};"
        : "+f"(c[0]), "+f"(c[1]), "+f"(c[2]), "+f"(c[3])
        : "r"(a[0]), "r"(a[1]), "r"(a[2]), "r"(a[3]), "r"(b[0]), "r"(b[1]));
}

// ---------------------------------------------------------------------------
// Weight prep: fp32 [K,N] -> bf16 transposed [N,K]
// ---------------------------------------------------------------------------
__global__ void wprep_kernel(const float* __restrict__ W,
                             __nv_bfloat16* __restrict__ dst, int K, int N) {
    int idx = blockIdx.x * blockDim.x + threadIdx.x;
    if (idx >= K * N) return;
    int k = idx / N, n = idx % N;
    dst[(size_t)n * K + k] = __float2bfloat16(W[idx]);
}

// ---------------------------------------------------------------------------
// Relative-position-bias expansion into padded [4][112][112] table
// ---------------------------------------------------------------------------
__global__ void bias_expand_kernel(const float* __restrict__ rpb) {
    int idx = blockIdx.x * blockDim.x + threadIdx.x;
    if (idx >= 4 * 112 * 112) return;
    int h = idx / (112 * 112);
    int r = idx % (112 * 112);
    int i = r / 112, j = r % 112;
    float v = 0.f;
    if (i < NTOK && j < NTOK) {
        int ti = i / 49, hi = (i / 7) % 7, wi = i % 7;
        int tj = j / 49, hj = (j / 7) % 7, wj = j % 7;
        int ridx = (ti - tj + 1) * 169 + (hi - hj + 6) * 13 + (wi - wj + 6);
        v = rpb[ridx * 4 + h];
    }
    g_biasNN[idx] = v;
}

// ---------------------------------------------------------------------------
// LN1 + shift + window partition -> bf16
// ---------------------------------------------------------------------------
__global__ void ln_gather_kernel(const float* __restrict__ x,
                                 const float* __restrict__ g,
                                 const float* __restrict__ bta,
                                 __nv_bfloat16* __restrict__ out) {
    int warp = threadIdx.x >> 5, lane = threadIdx.x & 31;
    int row = blockIdx.x * 8 + warp;
    int bwin = row / NTOK, n = row % NTOK;
    int b = bwin >> 8, win = bwin & 255;
    int tw = win >> 6, hw = (win >> 3) & 7, ww = win & 7;
    int t0 = n / 49, r49 = n % 49, h0 = r49 / 7, w0 = r49 % 7;
    int tg = (tw * 2 + t0 + 1) & 7;
    int hg = hw * 7 + h0 + 3; if (hg >= 56) hg -= 56;
    int wg = ww * 7 + w0 + 3; if (wg >= 56) wg -= 56;
    const float* src = x + ((size_t)b * LTOK + (size_t)(tg * 56 + hg) * 56 + wg) * CC;

    float v[4]; float s = 0.f;
#pragma unroll
    for (int k = 0; k < 4; k++) { v[k] = src[lane + 32 * k]; s += v[k]; }
#pragma unroll
    for (int o = 16; o > 0; o >>= 1) s += __shfl_xor_sync(0xffffffffu, s, o);
    float mean = s * (1.0f / CC);
    float q = 0.f;
#pragma unroll
    for (int k = 0; k < 4; k++) { float d = v[k] - mean; q += d * d; }
#pragma unroll
    for (int o = 16; o > 0; o >>= 1) q += __shfl_xor_sync(0xffffffffu, q, o);
    float rstd = rsqrtf(q * (1.0f / CC) + EPS);
    __nv_bfloat16* dst = out + (size_t)row * CC;
#pragma unroll
    for (int k = 0; k < 4; k++) {
        int c = lane + 32 * k;
        dst[c] = __float2bfloat16((v[k] - mean) * rstd * g[c] + bta[c]);
    }
}

// ---------------------------------------------------------------------------
// HMMA GEMM: out[M,N] = A[M,K] @ W + bias (+epi)
// ---------------------------------------------------------------------------
#define SSTR 40   // smem row stride in bf16 elems

__global__ __launch_bounds__(256) void gemm_mma_kernel(
        const __nv_bfloat16* __restrict__ A, const __nv_bfloat16* __restrict__ Wt,
        const float* __restrict__ bias, const float* __restrict__ resid,
        void* __restrict__ outv, int M, int Np, int K, int epi, int out_bf16) {
    __shared__ __align__(16) __nv_bfloat16 sA[128 * SSTR];
    __shared__ __align__(16) __nv_bfloat16 sB[128 * SSTR];

    int t = threadIdx.x;
    int warp = t >> 5, lane = t & 31;
    int wm = warp & 1, wn = warp >> 1;
    int gid = lane >> 2, tig = lane & 3;
    int n0 = blockIdx.x << 7, m0 = blockIdx.y << 7;

    float acc[4][4][4];
#pragma unroll
    for (int mt = 0; mt < 4; mt++)
#pragma unroll
        for (int nt = 0; nt < 4; nt++)
#pragma unroll
            for (int e = 0; e < 4; e++) acc[mt][nt][e] = 0.f;

    int lr = t >> 2;
    int lc = (t & 3) << 3;

    const __nv_bfloat16* Ag = A + (size_t)(m0 + lr) * K + lc;
    const __nv_bfloat16* Bg = Wt + (size_t)(n0 + lr) * K + lc;

    int nk = K >> 5;
    float4 pa0 = *(const float4*)Ag;
    float4 pa1 = *(const float4*)(Ag + (size_t)64 * K);
    float4 pb0 = *(const float4*)Bg;
    float4 pb1 = *(const float4*)(Bg + (size_t)64 * K);

    for (int kc = 0; kc < nk; kc++) {
        *(float4*)&sA[lr * SSTR + lc] = pa0;
        *(float4*)&sA[(lr + 64) * SSTR + lc] = pa1;
        *(float4*)&sB[lr * SSTR + lc] = pb0;
        *(float4*)&sB[(lr + 64) * SSTR + lc] = pb1;
        __syncthreads();
        if (kc + 1 < nk) {
            int kt = (kc + 1) << 5;
            pa0 = *(const float4*)(Ag + kt);
            pa1 = *(const float4*)(Ag + (size_t)64 * K + kt);
            pb0 = *(const float4*)(Bg + kt);
            pb1 = *(const float4*)(Bg + (size_t)64 * K + kt);
        }
#pragma unroll
        for (int ks = 0; ks < 2; ks++) {
            int k0 = ks << 4;
            uint32_t af[4][4], bf[4][2];
#pragma unroll
            for (int mt = 0; mt < 4; mt++) {
                int base = (wm * 64 + mt * 16 + gid) * SSTR + k0 + tig * 2;
                af[mt][0] = *(const uint32_t*)&sA[base];
                af[mt][1] = *(const uint32_t*)&sA[base + 8 * SSTR];
                af[mt][2] = *(const uint32_t*)&sA[base + 8];
                af[mt][3] = *(const uint32_t*)&sA[base + 8 * SSTR + 8];
            }
#pragma unroll
            for (int nt = 0; nt < 4; nt++) {
                int base = (wn * 32 + nt * 8 + gid) * SSTR + k0 + tig * 2;
                bf[nt][0] = *(const uint32_t*)&sB[base];
                bf[nt][1] = *(const uint32_t*)&sB[base + 8];
            }
#pragma unroll
            for (int mt = 0; mt < 4; mt++)
#pragma unroll
                for (int nt = 0; nt < 4; nt++)
                    mma16816(acc[mt][nt], af[mt], bf[nt]);
        }
        __syncthreads();
    }

#pragma unroll
    for (int mt = 0; mt < 4; mt++) {
        int row = m0 + wm * 64 + mt * 16 + gid;
#pragma unroll
        for (int nt = 0; nt < 4; nt++) {
            int col = n0 + wn * 32 + nt * 8 + tig * 2;
            float b0 = bias[col], b1 = bias[col + 1];
            float v00 = acc[mt][nt][0] + b0, v01 = acc[mt][nt][1] + b1;
            float v10 = acc[mt][nt][2] + b0, v11 = acc[mt][nt][3] + b1;
            if (epi == 1) {
                v00 = 0.5f * v00 * (1.0f + erff(v00 * 0.7071067811865475f));
                v01 = 0.5f * v01 * (1.0f + erff(v01 * 0.7071067811865475f));
                v10 = 0.5f * v10 * (1.0f + erff(v10 * 0.7071067811865475f));
                v11 = 0.5f * v11 * (1.0f + erff(v11 * 0.7071067811865475f));
            }
            size_t o0 = (size_t)row * Np + col;
            size_t o1 = (size_t)(row + 8) * Np + col;
            if (epi == 2) {
                float2 r0 = *(const float2*)(resid + o0);
                float2 r1 = *(const float2*)(resid + o1);
                v00 += r0.x; v01 += r0.y; v10 += r1.x; v11 += r1.y;
            }
            if (out_bf16) {
                __nv_bfloat16* op = (__nv_bfloat16*)outv;
                *(__nv_bfloat162*)(op + o0) = __floats2bfloat162_rn(v00, v01);
                *(__nv_bfloat162*)(op + o1) = __floats2bfloat162_rn(v10, v11);
            } else {
                float* op = (float*)outv;
                *(float2*)(op + o0) = make_float2(v00, v01);
                *(float2*)(op + o1) = make_float2(v10, v11);
            }
        }
    }
}

// ---------------------------------------------------------------------------
// HMMA attention: one CTA per (window, head). 256 threads (8 warps).
// Tokens padded 98 -> 112 (7 m-tiles). Warps 0..6 own one 16-row m-tile.
// S held in registers; softmax via quad shuffles; P stored bf16 for PV.
// ---------------------------------------------------------------------------
#define QSTR 40
#define PSTR 120
#define ASMEM_ELEMS (2 * 112 * QSTR + 32 * PSTR + 112 * PSTR)   // 26240 bf16

__global__ __launch_bounds__(256) void attn_mma_kernel(
        const __nv_bfloat16* __restrict__ qkv, __nv_bfloat16* __restrict__ out) {
    extern __shared__ __align__(16) __nv_bfloat16 smem[];
    __nv_bfloat16* sQ  = smem;                  // [112][QSTR]
    __nv_bfloat16* sK  = sQ + 112 * QSTR;       // [112][QSTR]
    __nv_bfloat16* sVt = sK + 112 * QSTR;       // [32][PSTR]  (V transposed)
    __nv_bfloat16* sP  = sVt + 32 * PSTR;       // [112][PSTR]
    __shared__ int sreg[112];

    int bwin = blockIdx.x >> 2, head = blockIdx.x & 3;
    int tid = threadIdx.x, warp = tid >> 5, lane = tid & 31;
    int gid = lane >> 2, tig = lane & 3;

    size_t base = (size_t)bwin * NTOK * 384 + head * 32;
    // Q, K rows 0..97
    for (int idx = tid; idx < 98 * 16; idx += 256) {
        int n = idx >> 4, d2 = (idx & 15) << 1;
        size_t o = base + (size_t)n * 384 + d2;
        *(uint32_t*)&sQ[n * QSTR + d2] = *(const uint32_t*)(qkv + o);
        *(uint32_t*)&sK[n * QSTR + d2] = *(const uint32_t*)(qkv + o + 128);
    }
    // V transposed
    for (int idx = tid; idx < 98 * 32; idx += 256) {
        int n = idx >> 5, d = idx & 31;
        sVt[d * PSTR + n] = qkv[base + (size_t)n * 384 + 256 + d];
    }
    // zero pads: Q/K rows 98..111 (cols 0..31), Vt cols 98..111
    for (int idx = tid; idx < 14 * 16; idx += 256) {
        int r = 98 + (idx >> 4), d2 = (idx & 15) << 1;
        *(uint32_t*)&sQ[r * QSTR + d2] = 0u;
        *(uint32_t*)&sK[r * QSTR + d2] = 0u;
    }
    for (int idx = tid; idx < 32 * 14; idx += 256) {
        int d = idx / 14, n = 98 + idx % 14;
        sVt[d * PSTR + n] = __float2bfloat16(0.f);
    }
    if (tid < 112) {
        int v = 0;
        if (tid < 98) {
            int win = bwin & 255;
            int tw = win >> 6, hw = (win >> 3) & 7, ww = win & 7;
            int t0 = tid / 49, r = tid % 49, h0 = r / 7, w0 = r % 7;
            int tg = tw * 2 + t0, hg = hw * 7 + h0, wg = ww * 7 + w0;
            int rt = tg < 6 ? 0 : (tg < 7 ? 1 : 2);
            int rh = hg < 49 ? 0 : (hg < 53 ? 1 : 2);
            int rw = wg < 49 ? 0 : (wg < 53 ? 1 : 2);
            v = rt * 9 + rh * 3 + rw;
        }
        sreg[tid] = v;
    }
    __syncthreads();

    if (warp < 7) {
        int mrow = warp << 4;
        float acc[14][4];
#pragma unroll
        for (int n = 0; n < 14; n++)
#pragma unroll
            for (int e = 0; e < 4; e++) acc[n][e] = 0.f;

        // S = Q K^T
#pragma unroll
        for (int ks = 0; ks < 2; ks++) {
            int k0 = ks << 4;
            uint32_t af[4];
            const __nv_bfloat16* qb = sQ + (mrow + gid) * QSTR + k0 + tig * 2;
            af[0] = *(const uint32_t*)qb;
            af[1] = *(const uint32_t*)(qb + 8 * QSTR);
            af[2] = *(const uint32_t*)(qb + 8);
            af[3] = *(const uint32_t*)(qb + 8 * QSTR + 8);
#pragma unroll
            for (int n = 0; n < 14; n++) {
                uint32_t bf[2];
                const __nv_bfloat16* kb = sK + (n * 8 + gid) * QSTR + k0 + tig * 2;
                bf[0] = *(const uint32_t*)kb;
                bf[1] = *(const uint32_t*)(kb + 8);
                mma16816(acc[n], af, bf);
            }
        }

        // bias + mask + softmax (rows r0 = mrow+gid, r1 = r0+8)
        int r0 = mrow + gid, r1 = r0 + 8;
        const float* bh = g_biasNN + head * (112 * 112);
        int ri0 = sreg[r0], ri1 = sreg[r1];
        float mx0 = -1e30f, mx1 = -1e30f;
#pragma unroll
        for (int n = 0; n < 14; n++) {
            int col = n * 8 + tig * 2;
            float2 b0 = *(const float2*)(bh + r0 * 112 + col);
            float2 b1 = *(const float2*)(bh + r1 * 112 + col);
            int rj0 = sreg[col], rj1 = sreg[col + 1];
            acc[n][0] = acc[n][0] * SCALE + b0.x + (ri0 != rj0 ? -100.f : 0.f);
            acc[n][1] = acc[n][1] * SCALE + b0.y + (ri0 != rj1 ? -100.f : 0.f);
            acc[n][2] = acc[n][2] * SCALE + b1.x + (ri1 != rj0 ? -100.f : 0.f);
            acc[n][3] = acc[n][3] * SCALE + b1.y + (ri1 != rj1 ? -100.f : 0.f);
            if (col < 98)     { mx0 = fmaxf(mx0, acc[n][0]); mx1 = fmaxf(mx1, acc[n][2]); }
            if (col + 1 < 98) { mx0 = fmaxf(mx0, acc[n][1]); mx1 = fmaxf(mx1, acc[n][3]); }
        }
        mx0 = fmaxf(mx0, __shfl_xor_sync(0xffffffffu, mx0, 1));
        mx0 = fmaxf(mx0, __shfl_xor_sync(0xffffffffu, mx0, 2));
        mx1 = fmaxf(mx1, __shfl_xor_sync(0xffffffffu, mx1, 1));
        mx1 = fmaxf(mx1, __shfl_xor_sync(0xffffffffu, mx1, 2));
        float sm0 = 0.f, sm1 = 0.f;
#pragma unroll
        for (int n = 0; n < 14; n++) {
            int col = n * 8 + tig * 2;
            float e0 = (col < 98)     ? __expf(acc[n][0] - mx0) : 0.f;
            float e1 = (col + 1 < 98) ? __expf(acc[n][1] - mx0) : 0.f;
            float e2 = (col < 98)     ? __expf(acc[n][2] - mx1) : 0.f;
            float e3 = (col + 1 < 98) ? __expf(acc[n][3] - mx1) : 0.f;
            acc[n][0] = e0; acc[n][1] = e1; acc[n][2] = e2; acc[n][3] = e3;
            sm0 += e0 + e1; sm1 += e2 + e3;
        }
        sm0 += __shfl_xor_sync(0xffffffffu, sm0, 1);
        sm0 += __shfl_xor_sync(0xffffffffu, sm0, 2);
        sm1 += __shfl_xor_sync(0xffffffffu, sm1, 1);
        sm1 += __shfl_xor_sync(0xffffffffu, sm1, 2);
        float inv0 = 1.f / sm0, inv1 = 1.f / sm1;
#pragma unroll
        for (int n = 0; n < 14; n++) {
            int col = n * 8 + tig * 2;
            __nv_bfloat162 p0 = __floats2bfloat162_rn(acc[n][0] * inv0, acc[n][1] * inv0);
            __nv_bfloat162 p1 = __floats2bfloat162_rn(acc[n][2] * inv1, acc[n][3] * inv1);
            *(__nv_bfloat162*)&sP[r0 * PSTR + col] = p0;
            *(__nv_bfloat162*)&sP[r1 * PSTR + col] = p1;
        }
    }
    __syncthreads();

    // O = P V
    if (warp < 7) {
        int mrow = warp << 4;
        float oacc[4][4];
#pragma unroll
        for (int n = 0; n < 4; n++)
#pragma unroll
            for (int e = 0; e < 4; e++) oacc[n][e] = 0.f;
#pragma unroll
        for (int ks = 0; ks < 7; ks++) {
            int k0 = ks << 4;
            uint32_t af[4];
            const __nv_bfloat16* pb = sP + (mrow + gid) * PSTR + k0 + tig * 2;
            af[0] = *(const uint32_t*)pb;
            af[1] = *(const uint32_t*)(pb + 8 * PSTR);
            af[2] = *(const uint32_t*)(pb + 8);
            af[3] = *(const uint32_t*)(pb + 8 * PSTR + 8);
#pragma unroll
            for (int n = 0; n < 4; n++) {
                uint32_t bf[2];
                const __nv_bfloat16* vb = sVt + (n * 8 + gid) * PSTR + k0 + tig * 2;
                bf[0] = *(const uint32_t*)vb;
                bf[1] = *(const uint32_t*)(vb + 8);
                mma16816(oacc[n], af, bf);
            }
        }
        size_t obase = (size_t)bwin * NTOK * CC + head * 32;
        int r0 = mrow + gid, r1 = r0 + 8;
#pragma unroll
        for (int n = 0; n < 4; n++) {
            int col = n * 8 + tig * 2;
            if (r0 < 98)
                *(__nv_bfloat162*)(out + obase + (size_t)r0 * CC + col) =
                    __floats2bfloat162_rn(oacc[n][0], oacc[n][1]);
            if (r1 < 98)
                *(__nv_bfloat162*)(out + obase + (size_t)r1 * CC + col) =
                    __floats2bfloat162_rn(oacc[n][2], oacc[n][3]);
        }
    }
}

// ---------------------------------------------------------------------------
// Fused: window_reverse + roll + shortcut add -> x2 (fp32) AND LN2 -> bf16
// ---------------------------------------------------------------------------
__global__ void scatter_ln2_kernel(const float* __restrict__ x,
                                   const float* __restrict__ projout,
                                   const float* __restrict__ g,
                                   const float* __restrict__ bta,
                                   float* __restrict__ x2out,
                                   __nv_bfloat16* __restrict__ lnout) {
    int warp = threadIdx.x >> 5, lane = threadIdx.x & 31;
    int row = blockIdx.x * 8 + warp;
    int b = row / LTOK, l = row % LTOK;
    int tg = l / 3136, rem = l % 3136;
    int hg = rem / 56, wg = rem % 56;
    int tp = (tg + 7) & 7;
    int hp = hg - 3; if (hp < 0) hp += 56;
    int wp = wg - 3; if (wp < 0) wp += 56;
    int win = (tp >> 1) * 64 + (hp / 7) * 8 + (wp / 7);
    int n = (tp & 1) * 49 + (hp % 7) * 7 + (wp % 7);
    const float* src = projout + ((size_t)(b * 256 + win) * NTOK + n) * CC;
    const float* xr = x + (size_t)row * CC;

    float v[4]; float s = 0.f;
#pragma unroll
    for (int k = 0; k < 4; k++) {
        int c = lane + 32 * k;
        v[k] = xr[c] + src[c];
        s += v[k];
    }
    float* dx2 = x2out + (size_t)row * CC;
#pragma unroll
    for (int k = 0; k < 4; k++) dx2[lane + 32 * k] = v[k];

#pragma unroll
    for (int o = 16; o > 0; o >>= 1) s += __shfl_xor_sync(0xffffffffu, s, o);
    float mean = s * (1.0f / CC);
    float q = 0.f;
#pragma unroll
    for (int k = 0; k < 4; k++) { float d = v[k] - mean; q += d * d; }
#pragma unroll
    for (int o = 16; o > 0; o >>= 1) q += __shfl_xor_sync(0xffffffffu, q, o);
    float rstd = rsqrtf(q * (1.0f / CC) + EPS);
    __nv_bfloat16* dst = lnout + (size_t)row * CC;
#pragma unroll
    for (int k = 0; k < 4; k++) {
        int c = lane + 32 * k;
        dst[c] = __float2bfloat16((v[k] - mean) * rstd * g[c] + bta[c]);
    }
}

// ---------------------------------------------------------------------------
// Launch
// ---------------------------------------------------------------------------
extern "C" void kernel_launch(void* const* d_in, const int* in_sizes, int n_in,
                              void* d_out, int out_size) {
    const float* x       = (const float*)d_in[0];
    const float* norm1_g = (const float*)d_in[1];
    const float* norm1_b = (const float*)d_in[2];
    const float* qkv_w   = (const float*)d_in[3];
    const float* qkv_b   = (const float*)d_in[4];
    const float* proj_w  = (const float*)d_in[5];
    const float* proj_b  = (const float*)d_in[6];
    const float* rpb     = (const float*)d_in[7];
    const float* norm2_g = (const float*)d_in[8];
    const float* norm2_b = (const float*)d_in[9];
    const float* fc1_w   = (const float*)d_in[10];
    const float* fc1_b   = (const float*)d_in[11];
    const float* fc2_w   = (const float*)d_in[12];
    const float* fc2_b   = (const float*)d_in[13];
    float* outp = (float*)d_out;

    __nv_bfloat16 *bh1, *bh2, *wt;
    float *bufB, *bufC;
    cudaGetSymbolAddress((void**)&bh1, g_bh1);
    cudaGetSymbolAddress((void**)&bh2, g_bh2);
    cudaGetSymbolAddress((void**)&wt, g_wt);
    cudaGetSymbolAddress((void**)&bufB, g_bufB);
    cudaGetSymbolAddress((void**)&bufC, g_bufC);

    cudaFuncSetAttribute(attn_mma_kernel, cudaFuncAttributeMaxDynamicSharedMemorySize,
                         ASMEM_ELEMS * 2);

    // weight prep + bias expansion
    wprep_kernel<<<(128 * 384 + 255) / 256, 256>>>(qkv_w, wt + WT_QKV, 128, 384);
    wprep_kernel<<<(128 * 128 + 255) / 256, 256>>>(proj_w, wt + WT_PROJ, 128, 128);
    wprep_kernel<<<(128 * 512 + 255) / 256, 256>>>(fc1_w, wt + WT_FC1, 128, 512);
    wprep_kernel<<<(512 * 128 + 255) / 256, 256>>>(fc2_w, wt + WT_FC2, 512, 128);
    bias_expand_kernel<<<(4 * 112 * 112 + 255) / 256, 256>>>(rpb);

    // LN1 + shift + partition -> bh2 (bf16)
    ln_gather_kernel<<<MROWS / 8, 256>>>(x, norm1_g, norm1_b, bh2);

    // QKV GEMM -> bh1 bf16 [M,384]
    {
        dim3 grid(3, MROWS / 128);
        gemm_mma_kernel<<<grid, 256>>>(bh2, wt + WT_QKV, qkv_b, nullptr,
                                       bh1, MROWS, 384, 128, 0, 1);
    }

    // attention -> bh2 bf16
    attn_mma_kernel<<<BWIN * 4, 256, ASMEM_ELEMS * 2>>>(bh1, bh2);

    // proj GEMM -> bufC fp32
    {
        dim3 grid(1, MROWS / 128);
        gemm_mma_kernel<<<grid, 256>>>(bh2, wt + WT_PROJ, proj_b, nullptr,
                                       bufC, MROWS, 128, 128, 0, 0);
    }

    // fused scatter + shortcut + LN2 -> bufB (x2, fp32) + bh2 (bf16)
    scatter_ln2_kernel<<<MROWS / 8, 256>>>(x, bufC, norm2_g, norm2_b, bufB, bh2);

    // FC1 + GELU -> bh1 bf16 [M,512]
    {
        dim3 grid(4, MROWS / 128);
        gemm_mma_kernel<<<grid, 256>>>(bh2, wt + WT_FC1, fc1_b, nullptr,
                                       bh1, MROWS, 512, 128, 1, 1);
    }

    // FC2 + residual -> d_out fp32
    {
        dim3 grid(1, MROWS / 128);
        gemm_mma_kernel<<<grid, 256>>>(bh1, wt + WT_FC2, fc2_b, bufB,
                                       outp, MROWS, 128, 512, 2, 0);
    }
}

// round 7
// speedup vs baseline: 4.3384x; 1.2861x over previous
#include <cuda_runtime.h>
#include <cuda_bf16.h>
#include <math.h>
#include <stdint.h>

// ---------------------------------------------------------------------------
// Problem constants
// ---------------------------------------------------------------------------
#define CC 128
#define NTOK 98
#define BWIN 2048
#define LTOK 25088
#define MROWS 200704
#define HID 512
#define SCALE 0.17677669529663687f
#define EPS 1e-5f

// ---------------------------------------------------------------------------
// Scratch
// ---------------------------------------------------------------------------
__device__ __nv_bfloat16 g_bh1[(size_t)MROWS * HID];  // qkv out (384) / fc1 out (512)
__device__ __nv_bfloat16 g_bh2[(size_t)MROWS * CC];   // ln1 out / attn out (window layout)
__device__ __nv_bfloat16 g_bh3[(size_t)MROWS * CC];   // ln2 out (token layout)
__device__ float g_bufB[(size_t)MROWS * CC];          // x2 residual (token layout)
__device__ float g_biasNN[4 * 112 * 112];             // padded rel-pos bias
__device__ __nv_bfloat16 g_wt[196608];                // transposed bf16 weights [N][K]

#define WT_QKV 0        // 384 x 128
#define WT_PROJ 49152   // 128 x 128
#define WT_FC1 65536    // 512 x 128
#define WT_FC2 131072   // 128 x 512

// ---------------------------------------------------------------------------
// HMMA helper: m16n8k16 row.col f32.bf16.bf16.f32 (baseline PTX, sm_80+)
// ---------------------------------------------------------------------------
__device__ __forceinline__ void mma16816(float* c, const uint32_t* a, const uint32_t* b) {
    asm volatile(
        "mma.sync.aligned.m16n8k16.row.col.f32.bf16.bf16.f32 "
        "{%0,%1,%2,%3}, {%4,%5,%6,%7}, {%8,%9}, {%0,%1,%2,%3};"
        : "+f"(c[0]), "+f"(c[1]), "+f"(c[2]), "+f"(c[3])
        : "r"(a[0]), "r"(a[1]), "r"(a[2]), "r"(a[3]), "r"(b[0]), "r"(b[1]));
}

// cp.async 16B
__device__ __forceinline__ void cp16(void* sdst, const void* gsrc) {
    uint32_t sa = (uint32_t)__cvta_generic_to_shared(sdst);
    asm volatile("cp.async.cg.shared.global [%0], [%1], 16;" :: "r"(sa), "l"(gsrc));
}
__device__ __forceinline__ void cp_commit() {
    asm volatile("cp.async.commit_group;");
}
template <int N>
__device__ __forceinline__ void cp_wait() {
    asm volatile("cp.async.wait_group %0;" :: "n"(N));
}

// ---------------------------------------------------------------------------
// Weight prep: fp32 [K,N] -> bf16 transposed [N,K]
// ---------------------------------------------------------------------------
__global__ void wprep_kernel(const float* __restrict__ W,
                             __nv_bfloat16* __restrict__ dst, int K, int N) {
    int idx = blockIdx.x * blockDim.x + threadIdx.x;
    if (idx >= K * N) return;
    int k = idx / N, n = idx % N;
    dst[(size_t)n * K + k] = __float2bfloat16(W[idx]);
}

// ---------------------------------------------------------------------------
// Relative-position-bias expansion into padded [4][112][112]
// ---------------------------------------------------------------------------
__global__ void bias_expand_kernel(const float* __restrict__ rpb) {
    int idx = blockIdx.x * blockDim.x + threadIdx.x;
    if (idx >= 4 * 112 * 112) return;
    int h = idx / (112 * 112);
    int r = idx % (112 * 112);
    int i = r / 112, j = r % 112;
    float v = 0.f;
    if (i < NTOK && j < NTOK) {
        int ti = i / 49, hi = (i / 7) % 7, wi = i % 7;
        int tj = j / 49, hj = (j / 7) % 7, wj = j % 7;
        int ridx = (ti - tj + 1) * 169 + (hi - hj + 6) * 13 + (wi - wj + 6);
        v = rpb[ridx * 4 + h];
    }
    g_biasNN[idx] = v;
}

// window-layout row -> token row (shift/roll gather mapping)
__device__ __forceinline__ int win2tok(int row) {
    int bwin = row / NTOK, n = row % NTOK;
    int b = bwin >> 8, win = bwin & 255;
    int tw = win >> 6, hw = (win >> 3) & 7, ww = win & 7;
    int t0 = n / 49, r49 = n % 49, h0 = r49 / 7, w0 = r49 % 7;
    int tg = (tw * 2 + t0 + 1) & 7;
    int hg = hw * 7 + h0 + 3; if (hg >= 56) hg -= 56;
    int wg = ww * 7 + w0 + 3; if (wg >= 56) wg -= 56;
    return b * LTOK + (tg * 56 + hg) * 56 + wg;
}

// ---------------------------------------------------------------------------
// LN1 + shift + window partition -> bf16
// ---------------------------------------------------------------------------
__global__ void ln_gather_kernel(const float* __restrict__ x,
                                 const float* __restrict__ g,
                                 const float* __restrict__ bta,
                                 __nv_bfloat16* __restrict__ out) {
    int warp = threadIdx.x >> 5, lane = threadIdx.x & 31;
    int row = blockIdx.x * 8 + warp;
    const float* src = x + (size_t)win2tok(row) * CC;

    float v[4]; float s = 0.f;
#pragma unroll
    for (int k = 0; k < 4; k++) { v[k] = src[lane + 32 * k]; s += v[k]; }
#pragma unroll
    for (int o = 16; o > 0; o >>= 1) s += __shfl_xor_sync(0xffffffffu, s, o);
    float mean = s * (1.0f / CC);
    float q = 0.f;
#pragma unroll
    for (int k = 0; k < 4; k++) { float d = v[k] - mean; q += d * d; }
#pragma unroll
    for (int o = 16; o > 0; o >>= 1) q += __shfl_xor_sync(0xffffffffu, q, o);
    float rstd = rsqrtf(q * (1.0f / CC) + EPS);
    __nv_bfloat16* dst = out + (size_t)row * CC;
#pragma unroll
    for (int k = 0; k < 4; k++) {
        int c = lane + 32 * k;
        dst[c] = __float2bfloat16((v[k] - mean) * rstd * g[c] + bta[c]);
    }
}

// ---------------------------------------------------------------------------
// HMMA GEMM, cp.async double-buffered.
// EPI: 0 bias, 1 bias+GELU, 2 bias+resid, 3 bias+scatter-resid+LN2 (proj).
// OUTBF: 1 = bf16 out, 0 = fp32 out.
// NOTE (EPI3): outv (LN2 out) MUST be a different buffer than A — the LN2
// writes are in token layout and would race with other CTAs' A reads.
// ---------------------------------------------------------------------------
#define SSTR 40
#define STAGE_BYTES (2 * 128 * SSTR * 2)   // A-tile + B-tile, 20480 B
#define GEMM_SMEM   (2 * STAGE_BYTES)      // 40960
#define PROJ_SMEM   (128 * 132 * 4)        // 67584 (epilogue reuse)

template <int EPI, int OUTBF>
__global__ __launch_bounds__(256) void gemm_mma_kernel(
        const __nv_bfloat16* __restrict__ A, const __nv_bfloat16* __restrict__ Wt,
        const float* __restrict__ bias, const float* __restrict__ resid,
        void* __restrict__ outv, int M, int Np, int K,
        const float* __restrict__ xres, const float* __restrict__ ln_g,
        const float* __restrict__ ln_b, float* __restrict__ x2out) {
    extern __shared__ __align__(16) char smem[];

    int t = threadIdx.x;
    int warp = t >> 5, lane = t & 31;
    int wm = warp & 1, wn = warp >> 1;
    int gid = lane >> 2, tig = lane & 3;
    int n0 = blockIdx.x << 7, m0 = blockIdx.y << 7;

    float acc[4][4][4];
#pragma unroll
    for (int mt = 0; mt < 4; mt++)
#pragma unroll
        for (int nt = 0; nt < 4; nt++)
#pragma unroll
            for (int e = 0; e < 4; e++) acc[mt][nt][e] = 0.f;

    int lr = t >> 2;
    int lc = (t & 3) << 3;

    const __nv_bfloat16* Ag = A + (size_t)(m0 + lr) * K + lc;
    const __nv_bfloat16* Bg = Wt + (size_t)(n0 + lr) * K + lc;
    int sa0 = (lr * SSTR + lc) * 2;
    int sa1 = ((lr + 64) * SSTR + lc) * 2;
    int nk = K >> 5;

    // prologue: stage 0
    {
        char* st = smem;
        cp16(st + sa0, Ag);
        cp16(st + sa1, Ag + (size_t)64 * K);
        cp16(st + 10240 + sa0, Bg);
        cp16(st + 10240 + sa1, Bg + (size_t)64 * K);
        cp_commit();
    }

    for (int kc = 0; kc < nk; kc++) {
        if (kc + 1 < nk) {
            char* st = smem + ((kc + 1) & 1) * STAGE_BYTES;
            int kt = (kc + 1) << 5;
            cp16(st + sa0, Ag + kt);
            cp16(st + sa1, Ag + (size_t)64 * K + kt);
            cp16(st + 10240 + sa0, Bg + kt);
            cp16(st + 10240 + sa1, Bg + (size_t)64 * K + kt);
            cp_commit();
            cp_wait<1>();
        } else {
            cp_wait<0>();
        }
        __syncthreads();
        const __nv_bfloat16* sA = (const __nv_bfloat16*)(smem + (kc & 1) * STAGE_BYTES);
        const __nv_bfloat16* sB = sA + 128 * SSTR;
#pragma unroll
        for (int ks = 0; ks < 2; ks++) {
            int k0 = ks << 4;
            uint32_t af[4][4], bf[4][2];
#pragma unroll
            for (int mt = 0; mt < 4; mt++) {
                int base = (wm * 64 + mt * 16 + gid) * SSTR + k0 + tig * 2;
                af[mt][0] = *(const uint32_t*)&sA[base];
                af[mt][1] = *(const uint32_t*)&sA[base + 8 * SSTR];
                af[mt][2] = *(const uint32_t*)&sA[base + 8];
                af[mt][3] = *(const uint32_t*)&sA[base + 8 * SSTR + 8];
            }
#pragma unroll
            for (int nt = 0; nt < 4; nt++) {
                int base = (wn * 32 + nt * 8 + gid) * SSTR + k0 + tig * 2;
                bf[nt][0] = *(const uint32_t*)&sB[base];
                bf[nt][1] = *(const uint32_t*)&sB[base + 8];
            }
#pragma unroll
            for (int mt = 0; mt < 4; mt++)
#pragma unroll
                for (int nt = 0; nt < 4; nt++)
                    mma16816(acc[mt][nt], af[mt], bf[nt]);
        }
        __syncthreads();
    }

    if (EPI == 3) {
        // proj-fused epilogue: spill to smem, then scatter+resid+LN2
        float* sout = (float*)smem;
#pragma unroll
        for (int mt = 0; mt < 4; mt++) {
            int row = wm * 64 + mt * 16 + gid;
#pragma unroll
            for (int nt = 0; nt < 4; nt++) {
                int col = wn * 32 + nt * 8 + tig * 2;
                float b0 = bias[col], b1 = bias[col + 1];
                sout[row * 132 + col] = acc[mt][nt][0] + b0;
                sout[row * 132 + col + 1] = acc[mt][nt][1] + b1;
                sout[(row + 8) * 132 + col] = acc[mt][nt][2] + b0;
                sout[(row + 8) * 132 + col + 1] = acc[mt][nt][3] + b1;
            }
        }
        __syncthreads();
        __nv_bfloat16* lnout = (__nv_bfloat16*)outv;
#pragma unroll
        for (int i = 0; i < 16; i++) {
            int row = warp * 16 + i;
            int tr = win2tok(m0 + row);
            const float* xr = xres + (size_t)tr * CC;
            float v[4]; float s = 0.f;
#pragma unroll
            for (int k = 0; k < 4; k++) {
                int c = lane + 32 * k;
                v[k] = sout[row * 132 + c] + xr[c];
                s += v[k];
            }
            float* dx2 = x2out + (size_t)tr * CC;
#pragma unroll
            for (int k = 0; k < 4; k++) dx2[lane + 32 * k] = v[k];
#pragma unroll
            for (int o = 16; o > 0; o >>= 1) s += __shfl_xor_sync(0xffffffffu, s, o);
            float mean = s * (1.0f / CC);
            float q = 0.f;
#pragma unroll
            for (int k = 0; k < 4; k++) { float d = v[k] - mean; q += d * d; }
#pragma unroll
            for (int o = 16; o > 0; o >>= 1) q += __shfl_xor_sync(0xffffffffu, q, o);
            float rstd = rsqrtf(q * (1.0f / CC) + EPS);
            __nv_bfloat16* dst = lnout + (size_t)tr * CC;
#pragma unroll
            for (int k = 0; k < 4; k++) {
                int c = lane + 32 * k;
                dst[c] = __float2bfloat16((v[k] - mean) * rstd * ln_g[c] + ln_b[c]);
            }
        }
        return;
    }

#pragma unroll
    for (int mt = 0; mt < 4; mt++) {
        int row = m0 + wm * 64 + mt * 16 + gid;
#pragma unroll
        for (int nt = 0; nt < 4; nt++) {
            int col = n0 + wn * 32 + nt * 8 + tig * 2;
            float b0 = bias[col], b1 = bias[col + 1];
            float v00 = acc[mt][nt][0] + b0, v01 = acc[mt][nt][1] + b1;
            float v10 = acc[mt][nt][2] + b0, v11 = acc[mt][nt][3] + b1;
            if (EPI == 1) {
                v00 = 0.5f * v00 * (1.0f + erff(v00 * 0.7071067811865475f));
                v01 = 0.5f * v01 * (1.0f + erff(v01 * 0.7071067811865475f));
                v10 = 0.5f * v10 * (1.0f + erff(v10 * 0.7071067811865475f));
                v11 = 0.5f * v11 * (1.0f + erff(v11 * 0.7071067811865475f));
            }
            size_t o0 = (size_t)row * Np + col;
            size_t o1 = (size_t)(row + 8) * Np + col;
            if (EPI == 2) {
                float2 r0 = *(const float2*)(resid + o0);
                float2 r1 = *(const float2*)(resid + o1);
                v00 += r0.x; v01 += r0.y; v10 += r1.x; v11 += r1.y;
            }
            if (OUTBF) {
                __nv_bfloat16* op = (__nv_bfloat16*)outv;
                *(__nv_bfloat162*)(op + o0) = __floats2bfloat162_rn(v00, v01);
                *(__nv_bfloat162*)(op + o1) = __floats2bfloat162_rn(v10, v11);
            } else {
                float* op = (float*)outv;
                *(float2*)(op + o0) = make_float2(v00, v01);
                *(float2*)(op + o1) = make_float2(v10, v11);
            }
        }
    }
}

// ---------------------------------------------------------------------------
// HMMA attention
// ---------------------------------------------------------------------------
#define QSTR 40
#define PSTR 120
#define ASMEM_ELEMS (2 * 112 * QSTR + 32 * PSTR + 112 * PSTR)

__global__ __launch_bounds__(256) void attn_mma_kernel(
        const __nv_bfloat16* __restrict__ qkv, __nv_bfloat16* __restrict__ out) {
    extern __shared__ __align__(16) __nv_bfloat16 asmem[];
    __nv_bfloat16* sQ  = asmem;
    __nv_bfloat16* sK  = sQ + 112 * QSTR;
    __nv_bfloat16* sVt = sK + 112 * QSTR;
    __nv_bfloat16* sP  = sVt + 32 * PSTR;
    __shared__ int sreg[112];

    int bwin = blockIdx.x >> 2, head = blockIdx.x & 3;
    int tid = threadIdx.x, warp = tid >> 5, lane = tid & 31;
    int gid = lane >> 2, tig = lane & 3;

    size_t base = (size_t)bwin * NTOK * 384 + head * 32;
    for (int idx = tid; idx < 98 * 16; idx += 256) {
        int n = idx >> 4, d2 = (idx & 15) << 1;
        size_t o = base + (size_t)n * 384 + d2;
        *(uint32_t*)&sQ[n * QSTR + d2] = *(const uint32_t*)(qkv + o);
        *(uint32_t*)&sK[n * QSTR + d2] = *(const uint32_t*)(qkv + o + 128);
    }
    for (int idx = tid; idx < 98 * 32; idx += 256) {
        int n = idx >> 5, d = idx & 31;
        sVt[d * PSTR + n] = qkv[base + (size_t)n * 384 + 256 + d];
    }
    for (int idx = tid; idx < 14 * 16; idx += 256) {
        int r = 98 + (idx >> 4), d2 = (idx & 15) << 1;
        *(uint32_t*)&sQ[r * QSTR + d2] = 0u;
        *(uint32_t*)&sK[r * QSTR + d2] = 0u;
    }
    for (int idx = tid; idx < 32 * 14; idx += 256) {
        int d = idx / 14, n = 98 + idx % 14;
        sVt[d * PSTR + n] = __float2bfloat16(0.f);
    }
    if (tid < 112) {
        int v = 0;
        if (tid < 98) {
            int win = bwin & 255;
            int tw = win >> 6, hw = (win >> 3) & 7, ww = win & 7;
            int t0 = tid / 49, r = tid % 49, h0 = r / 7, w0 = r % 7;
            int tg = tw * 2 + t0, hg = hw * 7 + h0, wg = ww * 7 + w0;
            int rt = tg < 6 ? 0 : (tg < 7 ? 1 : 2);
            int rh = hg < 49 ? 0 : (hg < 53 ? 1 : 2);
            int rw = wg < 49 ? 0 : (wg < 53 ? 1 : 2);
            v = rt * 9 + rh * 3 + rw;
        }
        sreg[tid] = v;
    }
    __syncthreads();

    if (warp < 7) {
        int mrow = warp << 4;
        float acc[14][4];
#pragma unroll
        for (int n = 0; n < 14; n++)
#pragma unroll
            for (int e = 0; e < 4; e++) acc[n][e] = 0.f;
#pragma unroll
        for (int ks = 0; ks < 2; ks++) {
            int k0 = ks << 4;
            uint32_t af[4];
            const __nv_bfloat16* qb = sQ + (mrow + gid) * QSTR + k0 + tig * 2;
            af[0] = *(const uint32_t*)qb;
            af[1] = *(const uint32_t*)(qb + 8 * QSTR);
            af[2] = *(const uint32_t*)(qb + 8);
            af[3] = *(const uint32_t*)(qb + 8 * QSTR + 8);
#pragma unroll
            for (int n = 0; n < 14; n++) {
                uint32_t bf[2];
                const __nv_bfloat16* kb = sK + (n * 8 + gid) * QSTR + k0 + tig * 2;
                bf[0] = *(const uint32_t*)kb;
                bf[1] = *(const uint32_t*)(kb + 8);
                mma16816(acc[n], af, bf);
            }
        }
        int r0 = mrow + gid, r1 = r0 + 8;
        const float* bh = g_biasNN + head * (112 * 112);
        int ri0 = sreg[r0], ri1 = sreg[r1];
        float mx0 = -1e30f, mx1 = -1e30f;
#pragma unroll
        for (int n = 0; n < 14; n++) {
            int col = n * 8 + tig * 2;
            float2 b0 = *(const float2*)(bh + r0 * 112 + col);
            float2 b1 = *(const float2*)(bh + r1 * 112 + col);
            int rj0 = sreg[col], rj1 = sreg[col + 1];
            acc[n][0] = acc[n][0] * SCALE + b0.x + (ri0 != rj0 ? -100.f : 0.f);
            acc[n][1] = acc[n][1] * SCALE + b0.y + (ri0 != rj1 ? -100.f : 0.f);
            acc[n][2] = acc[n][2] * SCALE + b1.x + (ri1 != rj0 ? -100.f : 0.f);
            acc[n][3] = acc[n][3] * SCALE + b1.y + (ri1 != rj1 ? -100.f : 0.f);
            if (col < 98)     { mx0 = fmaxf(mx0, acc[n][0]); mx1 = fmaxf(mx1, acc[n][2]); }
            if (col + 1 < 98) { mx0 = fmaxf(mx0, acc[n][1]); mx1 = fmaxf(mx1, acc[n][3]); }
        }
        mx0 = fmaxf(mx0, __shfl_xor_sync(0xffffffffu, mx0, 1));
        mx0 = fmaxf(mx0, __shfl_xor_sync(0xffffffffu, mx0, 2));
        mx1 = fmaxf(mx1, __shfl_xor_sync(0xffffffffu, mx1, 1));
        mx1 = fmaxf(mx1, __shfl_xor_sync(0xffffffffu, mx1, 2));
        float sm0 = 0.f, sm1 = 0.f;
#pragma unroll
        for (int n = 0; n < 14; n++) {
            int col = n * 8 + tig * 2;
            float e0 = (col < 98)     ? __expf(acc[n][0] - mx0) : 0.f;
            float e1 = (col + 1 < 98) ? __expf(acc[n][1] - mx0) : 0.f;
            float e2 = (col < 98)     ? __expf(acc[n][2] - mx1) : 0.f;
            float e3 = (col + 1 < 98) ? __expf(acc[n][3] - mx1) : 0.f;
            acc[n][0] = e0; acc[n][1] = e1; acc[n][2] = e2; acc[n][3] = e3;
            sm0 += e0 + e1; sm1 += e2 + e3;
        }
        sm0 += __shfl_xor_sync(0xffffffffu, sm0, 1);
        sm0 += __shfl_xor_sync(0xffffffffu, sm0, 2);
        sm1 += __shfl_xor_sync(0xffffffffu, sm1, 1);
        sm1 += __shfl_xor_sync(0xffffffffu, sm1, 2);
        float inv0 = 1.f / sm0, inv1 = 1.f / sm1;
#pragma unroll
        for (int n = 0; n < 14; n++) {
            int col = n * 8 + tig * 2;
            *(__nv_bfloat162*)&sP[r0 * PSTR + col] =
                __floats2bfloat162_rn(acc[n][0] * inv0, acc[n][1] * inv0);
            *(__nv_bfloat162*)&sP[r1 * PSTR + col] =
                __floats2bfloat162_rn(acc[n][2] * inv1, acc[n][3] * inv1);
        }
    }
    __syncthreads();

    if (warp < 7) {
        int mrow = warp << 4;
        float oacc[4][4];
#pragma unroll
        for (int n = 0; n < 4; n++)
#pragma unroll
            for (int e = 0; e < 4; e++) oacc[n][e] = 0.f;
#pragma unroll
        for (int ks = 0; ks < 7; ks++) {
            int k0 = ks << 4;
            uint32_t af[4];
            const __nv_bfloat16* pb = sP + (mrow + gid) * PSTR + k0 + tig * 2;
            af[0] = *(const uint32_t*)pb;
            af[1] = *(const uint32_t*)(pb + 8 * PSTR);
            af[2] = *(const uint32_t*)(pb + 8);
            af[3] = *(const uint32_t*)(pb + 8 * PSTR + 8);
#pragma unroll
            for (int n = 0; n < 4; n++) {
                uint32_t bf[2];
                const __nv_bfloat16* vb = sVt + (n * 8 + gid) * PSTR + k0 + tig * 2;
                bf[0] = *(const uint32_t*)vb;
                bf[1] = *(const uint32_t*)(vb + 8);
                mma16816(oacc[n], af, bf);
            }
        }
        size_t obase = (size_t)bwin * NTOK * CC + head * 32;
        int r0 = mrow + gid, r1 = r0 + 8;
#pragma unroll
        for (int n = 0; n < 4; n++) {
            int col = n * 8 + tig * 2;
            if (r0 < 98)
                *(__nv_bfloat162*)(out + obase + (size_t)r0 * CC + col) =
                    __floats2bfloat162_rn(oacc[n][0], oacc[n][1]);
            if (r1 < 98)
                *(__nv_bfloat162*)(out + obase + (size_t)r1 * CC + col) =
                    __floats2bfloat162_rn(oacc[n][2], oacc[n][3]);
        }
    }
}

// ---------------------------------------------------------------------------
// Launch
// ---------------------------------------------------------------------------
extern "C" void kernel_launch(void* const* d_in, const int* in_sizes, int n_in,
                              void* d_out, int out_size) {
    const float* x       = (const float*)d_in[0];
    const float* norm1_g = (const float*)d_in[1];
    const float* norm1_b = (const float*)d_in[2];
    const float* qkv_w   = (const float*)d_in[3];
    const float* qkv_b   = (const float*)d_in[4];
    const float* proj_w  = (const float*)d_in[5];
    const float* proj_b  = (const float*)d_in[6];
    const float* rpb     = (const float*)d_in[7];
    const float* norm2_g = (const float*)d_in[8];
    const float* norm2_b = (const float*)d_in[9];
    const float* fc1_w   = (const float*)d_in[10];
    const float* fc1_b   = (const float*)d_in[11];
    const float* fc2_w   = (const float*)d_in[12];
    const float* fc2_b   = (const float*)d_in[13];
    float* outp = (float*)d_out;

    __nv_bfloat16 *bh1, *bh2, *bh3, *wt;
    float *bufB;
    cudaGetSymbolAddress((void**)&bh1, g_bh1);
    cudaGetSymbolAddress((void**)&bh2, g_bh2);
    cudaGetSymbolAddress((void**)&bh3, g_bh3);
    cudaGetSymbolAddress((void**)&wt, g_wt);
    cudaGetSymbolAddress((void**)&bufB, g_bufB);

    cudaFuncSetAttribute(attn_mma_kernel, cudaFuncAttributeMaxDynamicSharedMemorySize,
                         ASMEM_ELEMS * 2);
    cudaFuncSetAttribute(gemm_mma_kernel<3, 1>,
                         cudaFuncAttributeMaxDynamicSharedMemorySize, PROJ_SMEM);

    // weight prep + bias expansion
    wprep_kernel<<<(128 * 384 + 255) / 256, 256>>>(qkv_w, wt + WT_QKV, 128, 384);
    wprep_kernel<<<(128 * 128 + 255) / 256, 256>>>(proj_w, wt + WT_PROJ, 128, 128);
    wprep_kernel<<<(128 * 512 + 255) / 256, 256>>>(fc1_w, wt + WT_FC1, 128, 512);
    wprep_kernel<<<(512 * 128 + 255) / 256, 256>>>(fc2_w, wt + WT_FC2, 512, 128);
    bias_expand_kernel<<<(4 * 112 * 112 + 255) / 256, 256>>>(rpb);

    // LN1 + shift + partition -> bh2 (bf16, window layout)
    ln_gather_kernel<<<MROWS / 8, 256>>>(x, norm1_g, norm1_b, bh2);

    // QKV GEMM -> bh1 bf16 [M,384]
    {
        dim3 grid(3, MROWS / 128);
        gemm_mma_kernel<0, 1><<<grid, 256, GEMM_SMEM>>>(
            bh2, wt + WT_QKV, qkv_b, nullptr, bh1, MROWS, 384, 128,
            nullptr, nullptr, nullptr, nullptr);
    }

    // attention -> bh2 bf16 (window layout)
    attn_mma_kernel<<<BWIN * 4, 256, ASMEM_ELEMS * 2>>>(bh1, bh2);

    // proj GEMM fused with scatter + residual + LN2:
    //   A = bh2 (window layout), writes x2 -> bufB (fp32, token layout),
    //   ln2 -> bh3 (bf16, token layout). bh3 != bh2 avoids the R5 race.
    {
        dim3 grid(1, MROWS / 128);
        gemm_mma_kernel<3, 1><<<grid, 256, PROJ_SMEM>>>(
            bh2, wt + WT_PROJ, proj_b, nullptr, bh3, MROWS, 128, 128,
            x, norm2_g, norm2_b, bufB);
    }

    // FC1 + GELU -> bh1 bf16 [M,512] (token layout)
    {
        dim3 grid(4, MROWS / 128);
        gemm_mma_kernel<1, 1><<<grid, 256, GEMM_SMEM>>>(
            bh3, wt + WT_FC1, fc1_b, nullptr, bh1, MROWS, 512, 128,
            nullptr, nullptr, nullptr, nullptr);
    }

    // FC2 + residual(x2) -> d_out fp32 (token layout)
    {
        dim3 grid(1, MROWS / 128);
        gemm_mma_kernel<2, 0><<<grid, 256, GEMM_SMEM>>>(
            bh1, wt + WT_FC2, fc2_b, bufB, outp, MROWS, 128, 512,
            nullptr, nullptr, nullptr, nullptr);
    }
}

// round 8
// speedup vs baseline: 4.5048x; 1.0384x over previous
#include <cuda_runtime.h>
#include <cuda_bf16.h>
#include <math.h>
#include <stdint.h>

// ---------------------------------------------------------------------------
// Problem constants
// ---------------------------------------------------------------------------
#define CC 128
#define NTOK 98
#define BWIN 2048
#define LTOK 25088
#define MROWS 200704
#define HID 512
#define SCALE 0.17677669529663687f
#define EPS 1e-5f

// ---------------------------------------------------------------------------
// Scratch
// ---------------------------------------------------------------------------
__device__ __nv_bfloat16 g_bh1[(size_t)MROWS * HID];  // qkv out (384) / fc1 out (512)
__device__ __nv_bfloat16 g_bh2[(size_t)MROWS * CC];   // ln1 out / attn out (window layout)
__device__ __nv_bfloat16 g_bh3[(size_t)MROWS * CC];   // ln2 out (token layout)
__device__ float g_bufB[(size_t)MROWS * CC];          // x2 residual (token layout)
__device__ float g_biasNN[4 * 112 * 112];             // padded rel-pos bias
__device__ __nv_bfloat16 g_wt[196608];                // transposed bf16 weights [N][K]

#define WT_QKV 0        // 384 x 128
#define WT_PROJ 49152   // 128 x 128
#define WT_FC1 65536    // 512 x 128
#define WT_FC2 131072   // 128 x 512

// ---------------------------------------------------------------------------
// HMMA helper: m16n8k16 row.col f32.bf16.bf16.f32 (baseline PTX, sm_80+)
// ---------------------------------------------------------------------------
__device__ __forceinline__ void mma16816(float* c, const uint32_t* a, const uint32_t* b) {
    asm volatile(
        "mma.sync.aligned.m16n8k16.row.col.f32.bf16.bf16.f32 "
        "{%0,%1,%2,%3}, {%4,%5,%6,%7}, {%8,%9}, {%0,%1,%2,%3};"
        : "+f"(c[0]), "+f"(c[1]), "+f"(c[2]), "+f"(c[3])
        : "r"(a[0]), "r"(a[1]), "r"(a[2]), "r"(a[3]), "r"(b[0]), "r"(b[1]));
}

// cp.async 16B
__device__ __forceinline__ void cp16(void* sdst, const void* gsrc) {
    uint32_t sa = (uint32_t)__cvta_generic_to_shared(sdst);
    asm volatile("cp.async.cg.shared.global [%0], [%1], 16;" :: "r"(sa), "l"(gsrc));
}
__device__ __forceinline__ void cp_commit() {
    asm volatile("cp.async.commit_group;");
}
template <int N>
__device__ __forceinline__ void cp_wait() {
    asm volatile("cp.async.wait_group %0;" :: "n"(N));
}

// ---------------------------------------------------------------------------
// Combined prep: 4 weight transposes + bias expansion in one launch.
// ---------------------------------------------------------------------------
#define PREP_QKV_END  49152
#define PREP_PROJ_END 65536
#define PREP_FC1_END  131072
#define PREP_FC2_END  196608
#define PREP_TOTAL    246784   // + 4*112*112

__global__ void prep_kernel(const float* __restrict__ qkv_w,
                            const float* __restrict__ proj_w,
                            const float* __restrict__ fc1_w,
                            const float* __restrict__ fc2_w,
                            const float* __restrict__ rpb) {
    int idx = blockIdx.x * blockDim.x + threadIdx.x;
    if (idx >= PREP_TOTAL) return;
    if (idx < PREP_QKV_END) {
        int l = idx; int k = l / 384, n = l % 384;
        g_wt[WT_QKV + n * 128 + k] = __float2bfloat16(qkv_w[l]);
    } else if (idx < PREP_PROJ_END) {
        int l = idx - PREP_QKV_END; int k = l / 128, n = l % 128;
        g_wt[WT_PROJ + n * 128 + k] = __float2bfloat16(proj_w[l]);
    } else if (idx < PREP_FC1_END) {
        int l = idx - PREP_PROJ_END; int k = l / 512, n = l % 512;
        g_wt[WT_FC1 + n * 128 + k] = __float2bfloat16(fc1_w[l]);
    } else if (idx < PREP_FC2_END) {
        int l = idx - PREP_FC1_END; int k = l / 128, n = l % 128;
        g_wt[WT_FC2 + n * 512 + k] = __float2bfloat16(fc2_w[l]);
    } else {
        int r = idx - PREP_FC2_END;
        int h = r / (112 * 112);
        int rr = r % (112 * 112);
        int i = rr / 112, j = rr % 112;
        float v = 0.f;
        if (i < NTOK && j < NTOK) {
            int ti = i / 49, hi = (i / 7) % 7, wi = i % 7;
            int tj = j / 49, hj = (j / 7) % 7, wj = j % 7;
            int ridx = (ti - tj + 1) * 169 + (hi - hj + 6) * 13 + (wi - wj + 6);
            v = rpb[ridx * 4 + h];
        }
        g_biasNN[h * 112 * 112 + rr] = v;
    }
}

// window-layout row -> token row (shift/roll gather mapping)
__device__ __forceinline__ int win2tok(int row) {
    int bwin = row / NTOK, n = row % NTOK;
    int b = bwin >> 8, win = bwin & 255;
    int tw = win >> 6, hw = (win >> 3) & 7, ww = win & 7;
    int t0 = n / 49, r49 = n % 49, h0 = r49 / 7, w0 = r49 % 7;
    int tg = (tw * 2 + t0 + 1) & 7;
    int hg = hw * 7 + h0 + 3; if (hg >= 56) hg -= 56;
    int wg = ww * 7 + w0 + 3; if (wg >= 56) wg -= 56;
    return b * LTOK + (tg * 56 + hg) * 56 + wg;
}

// ---------------------------------------------------------------------------
// LN1 + shift + window partition -> bf16
// ---------------------------------------------------------------------------
__global__ void ln_gather_kernel(const float* __restrict__ x,
                                 const float* __restrict__ g,
                                 const float* __restrict__ bta,
                                 __nv_bfloat16* __restrict__ out) {
    int warp = threadIdx.x >> 5, lane = threadIdx.x & 31;
    int row = blockIdx.x * 8 + warp;
    const float* src = x + (size_t)win2tok(row) * CC;

    float v[4]; float s = 0.f;
#pragma unroll
    for (int k = 0; k < 4; k++) { v[k] = src[lane + 32 * k]; s += v[k]; }
#pragma unroll
    for (int o = 16; o > 0; o >>= 1) s += __shfl_xor_sync(0xffffffffu, s, o);
    float mean = s * (1.0f / CC);
    float q = 0.f;
#pragma unroll
    for (int k = 0; k < 4; k++) { float d = v[k] - mean; q += d * d; }
#pragma unroll
    for (int o = 16; o > 0; o >>= 1) q += __shfl_xor_sync(0xffffffffu, q, o);
    float rstd = rsqrtf(q * (1.0f / CC) + EPS);
    __nv_bfloat16* dst = out + (size_t)row * CC;
#pragma unroll
    for (int k = 0; k < 4; k++) {
        int c = lane + 32 * k;
        dst[c] = __float2bfloat16((v[k] - mean) * rstd * g[c] + bta[c]);
    }
}

// ---------------------------------------------------------------------------
// N-loop GEMM for K=128: A tile resident in smem, loop NT n-tiles with
// double-buffered weight tiles. EPI: 0 bias, 1 bias+GELU. Output bf16.
// ---------------------------------------------------------------------------
#define NSTR 136                       // smem row stride (bf16) for K=128 tiles
#define NL_TILE_BYTES (128 * NSTR * 2) // 34816
#define NL_SMEM (3 * NL_TILE_BYTES)    // A + 2 B stages = 104448

template <int NT, int EPI>
__global__ __launch_bounds__(256) void gemm_nloop_kernel(
        const __nv_bfloat16* __restrict__ A, const __nv_bfloat16* __restrict__ Wt,
        const float* __restrict__ bias, __nv_bfloat16* __restrict__ out) {
    extern __shared__ __align__(16) char smem[];
    __nv_bfloat16* sA = (__nv_bfloat16*)smem;

    int t = threadIdx.x;
    int warp = t >> 5, lane = t & 31;
    int wm = warp & 1, wn = warp >> 1;
    int gid = lane >> 2, tig = lane & 3;
    int m0 = blockIdx.x << 7;
    const int Np = NT * 128;

    // A load: 2048 16B-chunks; chunk c -> row c>>4, col8 = (c&15)*8
    {
        const __nv_bfloat16* Ag = A + (size_t)m0 * 128;
#pragma unroll
        for (int it = 0; it < 8; it++) {
            int c = t + (it << 8);
            int r = c >> 4, c8 = (c & 15) << 3;
            cp16(&sA[r * NSTR + c8], Ag + (size_t)r * 128 + c8);
        }
        // B tile 0
        __nv_bfloat16* sB0 = (__nv_bfloat16*)(smem + NL_TILE_BYTES);
#pragma unroll
        for (int it = 0; it < 8; it++) {
            int c = t + (it << 8);
            int r = c >> 4, c8 = (c & 15) << 3;
            cp16(&sB0[r * NSTR + c8], Wt + (size_t)r * 128 + c8);
        }
        cp_commit();
    }

    for (int nt = 0; nt < NT; nt++) {
        if (nt + 1 < NT) {
            __nv_bfloat16* sBn = (__nv_bfloat16*)(smem + NL_TILE_BYTES
                                                  + ((nt + 1) & 1) * NL_TILE_BYTES);
            const __nv_bfloat16* Bg = Wt + (size_t)(nt + 1) * 128 * 128;
#pragma unroll
            for (int it = 0; it < 8; it++) {
                int c = t + (it << 8);
                int r = c >> 4, c8 = (c & 15) << 3;
                cp16(&sBn[r * NSTR + c8], Bg + (size_t)r * 128 + c8);
            }
            cp_commit();
            cp_wait<1>();
        } else {
            cp_wait<0>();
        }
        __syncthreads();
        const __nv_bfloat16* sB = (const __nv_bfloat16*)(smem + NL_TILE_BYTES
                                                         + (nt & 1) * NL_TILE_BYTES);
        float acc[4][4][4];
#pragma unroll
        for (int mt = 0; mt < 4; mt++)
#pragma unroll
            for (int ntx = 0; ntx < 4; ntx++)
#pragma unroll
                for (int e = 0; e < 4; e++) acc[mt][ntx][e] = 0.f;

#pragma unroll
        for (int ks = 0; ks < 8; ks++) {
            int k0 = ks << 4;
            uint32_t af[4][4], bf[4][2];
#pragma unroll
            for (int mt = 0; mt < 4; mt++) {
                int base = (wm * 64 + mt * 16 + gid) * NSTR + k0 + tig * 2;
                af[mt][0] = *(const uint32_t*)&sA[base];
                af[mt][1] = *(const uint32_t*)&sA[base + 8 * NSTR];
                af[mt][2] = *(const uint32_t*)&sA[base + 8];
                af[mt][3] = *(const uint32_t*)&sA[base + 8 * NSTR + 8];
            }
#pragma unroll
            for (int ntx = 0; ntx < 4; ntx++) {
                int base = (wn * 32 + ntx * 8 + gid) * NSTR + k0 + tig * 2;
                bf[ntx][0] = *(const uint32_t*)&sB[base];
                bf[ntx][1] = *(const uint32_t*)&sB[base + 8];
            }
#pragma unroll
            for (int mt = 0; mt < 4; mt++)
#pragma unroll
                for (int ntx = 0; ntx < 4; ntx++)
                    mma16816(acc[mt][ntx], af[mt], bf[ntx]);
        }
        __syncthreads();

        // epilogue for this n-tile
        int ncol0 = nt * 128;
#pragma unroll
        for (int mt = 0; mt < 4; mt++) {
            int row = m0 + wm * 64 + mt * 16 + gid;
#pragma unroll
            for (int ntx = 0; ntx < 4; ntx++) {
                int col = ncol0 + wn * 32 + ntx * 8 + tig * 2;
                float b0 = bias[col], b1 = bias[col + 1];
                float v00 = acc[mt][ntx][0] + b0, v01 = acc[mt][ntx][1] + b1;
                float v10 = acc[mt][ntx][2] + b0, v11 = acc[mt][ntx][3] + b1;
                if (EPI == 1) {
                    v00 = 0.5f * v00 * (1.0f + erff(v00 * 0.7071067811865475f));
                    v01 = 0.5f * v01 * (1.0f + erff(v01 * 0.7071067811865475f));
                    v10 = 0.5f * v10 * (1.0f + erff(v10 * 0.7071067811865475f));
                    v11 = 0.5f * v11 * (1.0f + erff(v11 * 0.7071067811865475f));
                }
                *(__nv_bfloat162*)(out + (size_t)row * Np + col) =
                    __floats2bfloat162_rn(v00, v01);
                *(__nv_bfloat162*)(out + (size_t)(row + 8) * Np + col) =
                    __floats2bfloat162_rn(v10, v11);
            }
        }
    }
}

// ---------------------------------------------------------------------------
// Pipelined HMMA GEMM (BK=32 double-buffered). EPI: 2 bias+resid (fp32 out),
// 3 bias+scatter-resid+LN2 (proj; bf16 lnout + fp32 x2out).
// ---------------------------------------------------------------------------
#define SSTR 40
#define STAGE_BYTES (2 * 128 * SSTR * 2)
#define GEMM_SMEM   (2 * STAGE_BYTES)
#define PROJ_SMEM   (128 * 132 * 4)

template <int EPI, int OUTBF>
__global__ __launch_bounds__(256) void gemm_mma_kernel(
        const __nv_bfloat16* __restrict__ A, const __nv_bfloat16* __restrict__ Wt,
        const float* __restrict__ bias, const float* __restrict__ resid,
        void* __restrict__ outv, int M, int Np, int K,
        const float* __restrict__ xres, const float* __restrict__ ln_g,
        const float* __restrict__ ln_b, float* __restrict__ x2out) {
    extern __shared__ __align__(16) char smem[];

    int t = threadIdx.x;
    int warp = t >> 5, lane = t & 31;
    int wm = warp & 1, wn = warp >> 1;
    int gid = lane >> 2, tig = lane & 3;
    int n0 = blockIdx.x << 7, m0 = blockIdx.y << 7;

    float acc[4][4][4];
#pragma unroll
    for (int mt = 0; mt < 4; mt++)
#pragma unroll
        for (int nt = 0; nt < 4; nt++)
#pragma unroll
            for (int e = 0; e < 4; e++) acc[mt][nt][e] = 0.f;

    int lr = t >> 2;
    int lc = (t & 3) << 3;

    const __nv_bfloat16* Ag = A + (size_t)(m0 + lr) * K + lc;
    const __nv_bfloat16* Bg = Wt + (size_t)(n0 + lr) * K + lc;
    int sa0 = (lr * SSTR + lc) * 2;
    int sa1 = ((lr + 64) * SSTR + lc) * 2;
    int nk = K >> 5;

    {
        char* st = smem;
        cp16(st + sa0, Ag);
        cp16(st + sa1, Ag + (size_t)64 * K);
        cp16(st + 10240 + sa0, Bg);
        cp16(st + 10240 + sa1, Bg + (size_t)64 * K);
        cp_commit();
    }

    for (int kc = 0; kc < nk; kc++) {
        if (kc + 1 < nk) {
            char* st = smem + ((kc + 1) & 1) * STAGE_BYTES;
            int kt = (kc + 1) << 5;
            cp16(st + sa0, Ag + kt);
            cp16(st + sa1, Ag + (size_t)64 * K + kt);
            cp16(st + 10240 + sa0, Bg + kt);
            cp16(st + 10240 + sa1, Bg + (size_t)64 * K + kt);
            cp_commit();
            cp_wait<1>();
        } else {
            cp_wait<0>();
        }
        __syncthreads();
        const __nv_bfloat16* sA = (const __nv_bfloat16*)(smem + (kc & 1) * STAGE_BYTES);
        const __nv_bfloat16* sB = sA + 128 * SSTR;
#pragma unroll
        for (int ks = 0; ks < 2; ks++) {
            int k0 = ks << 4;
            uint32_t af[4][4], bf[4][2];
#pragma unroll
            for (int mt = 0; mt < 4; mt++) {
                int base = (wm * 64 + mt * 16 + gid) * SSTR + k0 + tig * 2;
                af[mt][0] = *(const uint32_t*)&sA[base];
                af[mt][1] = *(const uint32_t*)&sA[base + 8 * SSTR];
                af[mt][2] = *(const uint32_t*)&sA[base + 8];
                af[mt][3] = *(const uint32_t*)&sA[base + 8 * SSTR + 8];
            }
#pragma unroll
            for (int nt = 0; nt < 4; nt++) {
                int base = (wn * 32 + nt * 8 + gid) * SSTR + k0 + tig * 2;
                bf[nt][0] = *(const uint32_t*)&sB[base];
                bf[nt][1] = *(const uint32_t*)&sB[base + 8];
            }
#pragma unroll
            for (int mt = 0; mt < 4; mt++)
#pragma unroll
                for (int nt = 0; nt < 4; nt++)
                    mma16816(acc[mt][nt], af[mt], bf[nt]);
        }
        __syncthreads();
    }

    if (EPI == 3) {
        float* sout = (float*)smem;
#pragma unroll
        for (int mt = 0; mt < 4; mt++) {
            int row = wm * 64 + mt * 16 + gid;
#pragma unroll
            for (int nt = 0; nt < 4; nt++) {
                int col = wn * 32 + nt * 8 + tig * 2;
                float b0 = bias[col], b1 = bias[col + 1];
                sout[row * 132 + col] = acc[mt][nt][0] + b0;
                sout[row * 132 + col + 1] = acc[mt][nt][1] + b1;
                sout[(row + 8) * 132 + col] = acc[mt][nt][2] + b0;
                sout[(row + 8) * 132 + col + 1] = acc[mt][nt][3] + b1;
            }
        }
        __syncthreads();
        __nv_bfloat16* lnout = (__nv_bfloat16*)outv;
#pragma unroll
        for (int i = 0; i < 16; i++) {
            int row = warp * 16 + i;
            int tr = win2tok(m0 + row);
            const float* xr = xres + (size_t)tr * CC;
            float v[4]; float s = 0.f;
#pragma unroll
            for (int k = 0; k < 4; k++) {
                int c = lane + 32 * k;
                v[k] = sout[row * 132 + c] + xr[c];
                s += v[k];
            }
            float* dx2 = x2out + (size_t)tr * CC;
#pragma unroll
            for (int k = 0; k < 4; k++) dx2[lane + 32 * k] = v[k];
#pragma unroll
            for (int o = 16; o > 0; o >>= 1) s += __shfl_xor_sync(0xffffffffu, s, o);
            float mean = s * (1.0f / CC);
            float q = 0.f;
#pragma unroll
            for (int k = 0; k < 4; k++) { float d = v[k] - mean; q += d * d; }
#pragma unroll
            for (int o = 16; o > 0; o >>= 1) q += __shfl_xor_sync(0xffffffffu, q, o);
            float rstd = rsqrtf(q * (1.0f / CC) + EPS);
            __nv_bfloat16* dst = lnout + (size_t)tr * CC;
#pragma unroll
            for (int k = 0; k < 4; k++) {
                int c = lane + 32 * k;
                dst[c] = __float2bfloat16((v[k] - mean) * rstd * ln_g[c] + ln_b[c]);
            }
        }
        return;
    }

#pragma unroll
    for (int mt = 0; mt < 4; mt++) {
        int row = m0 + wm * 64 + mt * 16 + gid;
#pragma unroll
        for (int nt = 0; nt < 4; nt++) {
            int col = n0 + wn * 32 + nt * 8 + tig * 2;
            float b0 = bias[col], b1 = bias[col + 1];
            float v00 = acc[mt][nt][0] + b0, v01 = acc[mt][nt][1] + b1;
            float v10 = acc[mt][nt][2] + b0, v11 = acc[mt][nt][3] + b1;
            size_t o0 = (size_t)row * Np + col;
            size_t o1 = (size_t)(row + 8) * Np + col;
            if (EPI == 2) {
                float2 r0 = *(const float2*)(resid + o0);
                float2 r1 = *(const float2*)(resid + o1);
                v00 += r0.x; v01 += r0.y; v10 += r1.x; v11 += r1.y;
            }
            if (OUTBF) {
                __nv_bfloat16* op = (__nv_bfloat16*)outv;
                *(__nv_bfloat162*)(op + o0) = __floats2bfloat162_rn(v00, v01);
                *(__nv_bfloat162*)(op + o1) = __floats2bfloat162_rn(v10, v11);
            } else {
                float* op = (float*)outv;
                *(float2*)(op + o0) = make_float2(v00, v01);
                *(float2*)(op + o1) = make_float2(v10, v11);
            }
        }
    }
}

// ---------------------------------------------------------------------------
// HMMA attention
// ---------------------------------------------------------------------------
#define QSTR 40
#define PSTR 120
#define ASMEM_ELEMS (2 * 112 * QSTR + 32 * PSTR + 112 * PSTR)

__global__ __launch_bounds__(256) void attn_mma_kernel(
        const __nv_bfloat16* __restrict__ qkv, __nv_bfloat16* __restrict__ out) {
    extern __shared__ __align__(16) __nv_bfloat16 asmem[];
    __nv_bfloat16* sQ  = asmem;
    __nv_bfloat16* sK  = sQ + 112 * QSTR;
    __nv_bfloat16* sVt = sK + 112 * QSTR;
    __nv_bfloat16* sP  = sVt + 32 * PSTR;
    __shared__ int sreg[112];

    int bwin = blockIdx.x >> 2, head = blockIdx.x & 3;
    int tid = threadIdx.x, warp = tid >> 5, lane = tid & 31;
    int gid = lane >> 2, tig = lane & 3;

    size_t base = (size_t)bwin * NTOK * 384 + head * 32;
    for (int idx = tid; idx < 98 * 16; idx += 256) {
        int n = idx >> 4, d2 = (idx & 15) << 1;
        size_t o = base + (size_t)n * 384 + d2;
        *(uint32_t*)&sQ[n * QSTR + d2] = *(const uint32_t*)(qkv + o);
        *(uint32_t*)&sK[n * QSTR + d2] = *(const uint32_t*)(qkv + o + 128);
    }
    for (int idx = tid; idx < 98 * 32; idx += 256) {
        int n = idx >> 5, d = idx & 31;
        sVt[d * PSTR + n] = qkv[base + (size_t)n * 384 + 256 + d];
    }
    for (int idx = tid; idx < 14 * 16; idx += 256) {
        int r = 98 + (idx >> 4), d2 = (idx & 15) << 1;
        *(uint32_t*)&sQ[r * QSTR + d2] = 0u;
        *(uint32_t*)&sK[r * QSTR + d2] = 0u;
    }
    for (int idx = tid; idx < 32 * 14; idx += 256) {
        int d = idx / 14, n = 98 + idx % 14;
        sVt[d * PSTR + n] = __float2bfloat16(0.f);
    }
    if (tid < 112) {
        int v = 0;
        if (tid < 98) {
            int win = bwin & 255;
            int tw = win >> 6, hw = (win >> 3) & 7, ww = win & 7;
            int t0 = tid / 49, r = tid % 49, h0 = r / 7, w0 = r % 7;
            int tg = tw * 2 + t0, hg = hw * 7 + h0, wg = ww * 7 + w0;
            int rt = tg < 6 ? 0 : (tg < 7 ? 1 : 2);
            int rh = hg < 49 ? 0 : (hg < 53 ? 1 : 2);
            int rw = wg < 49 ? 0 : (wg < 53 ? 1 : 2);
            v = rt * 9 + rh * 3 + rw;
        }
        sreg[tid] = v;
    }
    __syncthreads();

    if (warp < 7) {
        int mrow = warp << 4;
        float acc[14][4];
#pragma unroll
        for (int n = 0; n < 14; n++)
#pragma unroll
            for (int e = 0; e < 4; e++) acc[n][e] = 0.f;
#pragma unroll
        for (int ks = 0; ks < 2; ks++) {
            int k0 = ks << 4;
            uint32_t af[4];
            const __nv_bfloat16* qb = sQ + (mrow + gid) * QSTR + k0 + tig * 2;
            af[0] = *(const uint32_t*)qb;
            af[1] = *(const uint32_t*)(qb + 8 * QSTR);
            af[2] = *(const uint32_t*)(qb + 8);
            af[3] = *(const uint32_t*)(qb + 8 * QSTR + 8);
#pragma unroll
            for (int n = 0; n < 14; n++) {
                uint32_t bf[2];
                const __nv_bfloat16* kb = sK + (n * 8 + gid) * QSTR + k0 + tig * 2;
                bf[0] = *(const uint32_t*)kb;
                bf[1] = *(const uint32_t*)(kb + 8);
                mma16816(acc[n], af, bf);
            }
        }
        int r0 = mrow + gid, r1 = r0 + 8;
        const float* bh = g_biasNN + head * (112 * 112);
        int ri0 = sreg[r0], ri1 = sreg[r1];
        float mx0 = -1e30f, mx1 = -1e30f;
#pragma unroll
        for (int n = 0; n < 14; n++) {
            int col = n * 8 + tig * 2;
            float2 b0 = *(const float2*)(bh + r0 * 112 + col);
            float2 b1 = *(const float2*)(bh + r1 * 112 + col);
            int rj0 = sreg[col], rj1 = sreg[col + 1];
            acc[n][0] = acc[n][0] * SCALE + b0.x + (ri0 != rj0 ? -100.f : 0.f);
            acc[n][1] = acc[n][1] * SCALE + b0.y + (ri0 != rj1 ? -100.f : 0.f);
            acc[n][2] = acc[n][2] * SCALE + b1.x + (ri1 != rj0 ? -100.f : 0.f);
            acc[n][3] = acc[n][3] * SCALE + b1.y + (ri1 != rj1 ? -100.f : 0.f);
            if (col < 98)     { mx0 = fmaxf(mx0, acc[n][0]); mx1 = fmaxf(mx1, acc[n][2]); }
            if (col + 1 < 98) { mx0 = fmaxf(mx0, acc[n][1]); mx1 = fmaxf(mx1, acc[n][3]); }
        }
        mx0 = fmaxf(mx0, __shfl_xor_sync(0xffffffffu, mx0, 1));
        mx0 = fmaxf(mx0, __shfl_xor_sync(0xffffffffu, mx0, 2));
        mx1 = fmaxf(mx1, __shfl_xor_sync(0xffffffffu, mx1, 1));
        mx1 = fmaxf(mx1, __shfl_xor_sync(0xffffffffu, mx1, 2));
        float sm0 = 0.f, sm1 = 0.f;
#pragma unroll
        for (int n = 0; n < 14; n++) {
            int col = n * 8 + tig * 2;
            float e0 = (col < 98)     ? __expf(acc[n][0] - mx0) : 0.f;
            float e1 = (col + 1 < 98) ? __expf(acc[n][1] - mx0) : 0.f;
            float e2 = (col < 98)     ? __expf(acc[n][2] - mx1) : 0.f;
            float e3 = (col + 1 < 98) ? __expf(acc[n][3] - mx1) : 0.f;
            acc[n][0] = e0; acc[n][1] = e1; acc[n][2] = e2; acc[n][3] = e3;
            sm0 += e0 + e1; sm1 += e2 + e3;
        }
        sm0 += __shfl_xor_sync(0xffffffffu, sm0, 1);
        sm0 += __shfl_xor_sync(0xffffffffu, sm0, 2);
        sm1 += __shfl_xor_sync(0xffffffffu, sm1, 1);
        sm1 += __shfl_xor_sync(0xffffffffu, sm1, 2);
        float inv0 = 1.f / sm0, inv1 = 1.f / sm1;
#pragma unroll
        for (int n = 0; n < 14; n++) {
            int col = n * 8 + tig * 2;
            *(__nv_bfloat162*)&sP[r0 * PSTR + col] =
                __floats2bfloat162_rn(acc[n][0] * inv0, acc[n][1] * inv0);
            *(__nv_bfloat162*)&sP[r1 * PSTR + col] =
                __floats2bfloat162_rn(acc[n][2] * inv1, acc[n][3] * inv1);
        }
    }
    __syncthreads();

    if (warp < 7) {
        int mrow = warp << 4;
        float oacc[4][4];
#pragma unroll
        for (int n = 0; n < 4; n++)
#pragma unroll
            for (int e = 0; e < 4; e++) oacc[n][e] = 0.f;
#pragma unroll
        for (int ks = 0; ks < 7; ks++) {
            int k0 = ks << 4;
            uint32_t af[4];
            const __nv_bfloat16* pb = sP + (mrow + gid) * PSTR + k0 + tig * 2;
            af[0] = *(const uint32_t*)pb;
            af[1] = *(const uint32_t*)(pb + 8 * PSTR);
            af[2] = *(const uint32_t*)(pb + 8);
            af[3] = *(const uint32_t*)(pb + 8 * PSTR + 8);
#pragma unroll
            for (int n = 0; n < 4; n++) {
                uint32_t bf[2];
                const __nv_bfloat16* vb = sVt + (n * 8 + gid) * PSTR + k0 + tig * 2;
                bf[0] = *(const uint32_t*)vb;
                bf[1] = *(const uint32_t*)(vb + 8);
                mma16816(oacc[n], af, bf);
            }
        }
        size_t obase = (size_t)bwin * NTOK * CC + head * 32;
        int r0 = mrow + gid, r1 = r0 + 8;
#pragma unroll
        for (int n = 0; n < 4; n++) {
            int col = n * 8 + tig * 2;
            if (r0 < 98)
                *(__nv_bfloat162*)(out + obase + (size_t)r0 * CC + col) =
                    __floats2bfloat162_rn(oacc[n][0], oacc[n][1]);
            if (r1 < 98)
                *(__nv_bfloat162*)(out + obase + (size_t)r1 * CC + col) =
                    __floats2bfloat162_rn(oacc[n][2], oacc[n][3]);
        }
    }
}

// ---------------------------------------------------------------------------
// Launch
// ---------------------------------------------------------------------------
extern "C" void kernel_launch(void* const* d_in, const int* in_sizes, int n_in,
                              void* d_out, int out_size) {
    const float* x       = (const float*)d_in[0];
    const float* norm1_g = (const float*)d_in[1];
    const float* norm1_b = (const float*)d_in[2];
    const float* qkv_w   = (const float*)d_in[3];
    const float* qkv_b   = (const float*)d_in[4];
    const float* proj_w  = (const float*)d_in[5];
    const float* proj_b  = (const float*)d_in[6];
    const float* rpb     = (const float*)d_in[7];
    const float* norm2_g = (const float*)d_in[8];
    const float* norm2_b = (const float*)d_in[9];
    const float* fc1_w   = (const float*)d_in[10];
    const float* fc1_b   = (const float*)d_in[11];
    const float* fc2_w   = (const float*)d_in[12];
    const float* fc2_b   = (const float*)d_in[13];
    float* outp = (float*)d_out;

    __nv_bfloat16 *bh1, *bh2, *bh3, *wt;
    float *bufB;
    cudaGetSymbolAddress((void**)&bh1, g_bh1);
    cudaGetSymbolAddress((void**)&bh2, g_bh2);
    cudaGetSymbolAddress((void**)&bh3, g_bh3);
    cudaGetSymbolAddress((void**)&wt, g_wt);
    cudaGetSymbolAddress((void**)&bufB, g_bufB);

    cudaFuncSetAttribute(attn_mma_kernel, cudaFuncAttributeMaxDynamicSharedMemorySize,
                         ASMEM_ELEMS * 2);
    cudaFuncSetAttribute(gemm_mma_kernel<3, 1>,
                         cudaFuncAttributeMaxDynamicSharedMemorySize, PROJ_SMEM);
    cudaFuncSetAttribute(gemm_nloop_kernel<3, 0>,
                         cudaFuncAttributeMaxDynamicSharedMemorySize, NL_SMEM);
    cudaFuncSetAttribute(gemm_nloop_kernel<4, 1>,
                         cudaFuncAttributeMaxDynamicSharedMemorySize, NL_SMEM);

    // combined prep (weights transpose + bias expansion)
    prep_kernel<<<(PREP_TOTAL + 255) / 256, 256>>>(qkv_w, proj_w, fc1_w, fc2_w, rpb);

    // LN1 + shift + partition -> bh2 (bf16, window layout)
    ln_gather_kernel<<<MROWS / 8, 256>>>(x, norm1_g, norm1_b, bh2);

    // QKV GEMM (A-resident n-loop) -> bh1 bf16 [M,384]
    gemm_nloop_kernel<3, 0><<<MROWS / 128, 256, NL_SMEM>>>(
        bh2, wt + WT_QKV, qkv_b, bh1);

    // attention -> bh2 bf16 (window layout)
    attn_mma_kernel<<<BWIN * 4, 256, ASMEM_ELEMS * 2>>>(bh1, bh2);

    // proj GEMM fused with scatter + residual + LN2 -> bh3 (bf16), bufB (x2)
    {
        dim3 grid(1, MROWS / 128);
        gemm_mma_kernel<3, 1><<<grid, 256, PROJ_SMEM>>>(
            bh2, wt + WT_PROJ, proj_b, nullptr, bh3, MROWS, 128, 128,
            x, norm2_g, norm2_b, bufB);
    }

    // FC1 + GELU (A-resident n-loop) -> bh1 bf16 [M,512]
    gemm_nloop_kernel<4, 1><<<MROWS / 128, 256, NL_SMEM>>>(
        bh3, wt + WT_FC1, fc1_b, bh1);

    // FC2 + residual(x2) -> d_out fp32 (token layout)
    {
        dim3 grid(1, MROWS / 128);
        gemm_mma_kernel<2, 0><<<grid, 256, GEMM_SMEM>>>(
            bh1, wt + WT_FC2, fc2_b, bufB, outp, MROWS, 128, 512,
            nullptr, nullptr, nullptr, nullptr);
    }
}

// round 9
// speedup vs baseline: 5.4405x; 1.2077x over previous
#include <cuda_runtime.h>
#include <cuda_bf16.h>
#include <math.h>
#include <stdint.h>

// ---------------------------------------------------------------------------
// Problem constants
// ---------------------------------------------------------------------------
#define CC 128
#define NTOK 98
#define BWIN 2048
#define LTOK 25088
#define MROWS 200704
#define HID 512
#define SCALE 0.17677669529663687f
#define EPS 1e-5f

// ---------------------------------------------------------------------------
// Scratch
// ---------------------------------------------------------------------------
__device__ __nv_bfloat16 g_bh1[(size_t)MROWS * HID];  // qkv out (384) / fc1 out (512)
__device__ __nv_bfloat16 g_bh2[(size_t)MROWS * CC];   // ln1 out / attn out (window layout)
__device__ __nv_bfloat16 g_bh3[(size_t)MROWS * CC];   // ln2 out (token layout)
__device__ float g_bufB[(size_t)MROWS * CC];          // x2 residual (token layout)
__device__ float g_biasNN[4 * 112 * 112];             // padded rel-pos bias
__device__ __nv_bfloat16 g_wt[196608];                // transposed bf16 weights [N][K]

#define WT_QKV 0        // 384 x 128
#define WT_PROJ 49152   // 128 x 128
#define WT_FC1 65536    // 512 x 128
#define WT_FC2 131072   // 128 x 512

// ---------------------------------------------------------------------------
// HMMA helper: m16n8k16 row.col f32.bf16.bf16.f32 (baseline PTX, sm_80+)
// ---------------------------------------------------------------------------
__device__ __forceinline__ void mma16816(float* c, const uint32_t* a, const uint32_t* b) {
    asm volatile(
        "mma.sync.aligned.m16n8k16.row.col.f32.bf16.bf16.f32 "
        "{%0,%1,%2,%3}, {%4,%5,%6,%7}, {%8,%9}, {%0,%1,%2,%3};"
        : "+f"(c[0]), "+f"(c[1]), "+f"(c[2]), "+f"(c[3])
        : "r"(a[0]), "r"(a[1]), "r"(a[2]), "r"(a[3]), "r"(b[0]), "r"(b[1]));
}

// cp.async 16B
__device__ __forceinline__ void cp16(void* sdst, const void* gsrc) {
    uint32_t sa = (uint32_t)__cvta_generic_to_shared(sdst);
    asm volatile("cp.async.cg.shared.global [%0], [%1], 16;" :: "r"(sa), "l"(gsrc));
}
__device__ __forceinline__ void cp_commit() {
    asm volatile("cp.async.commit_group;");
}
template <int N>
__device__ __forceinline__ void cp_wait() {
    asm volatile("cp.async.wait_group %0;" :: "n"(N));
}

__device__ __forceinline__ uint32_t packbf2(float a, float b) {
    __nv_bfloat162 t = __floats2bfloat162_rn(a, b);
    return *(uint32_t*)&t;
}

// ---------------------------------------------------------------------------
// Combined prep: 4 weight transposes + bias expansion in one launch.
// ---------------------------------------------------------------------------
#define PREP_QKV_END  49152
#define PREP_PROJ_END 65536
#define PREP_FC1_END  131072
#define PREP_FC2_END  196608
#define PREP_TOTAL    246784   // + 4*112*112

__global__ void prep_kernel(const float* __restrict__ qkv_w,
                            const float* __restrict__ proj_w,
                            const float* __restrict__ fc1_w,
                            const float* __restrict__ fc2_w,
                            const float* __restrict__ rpb) {
    int idx = blockIdx.x * blockDim.x + threadIdx.x;
    if (idx >= PREP_TOTAL) return;
    if (idx < PREP_QKV_END) {
        int l = idx; int k = l / 384, n = l % 384;
        g_wt[WT_QKV + n * 128 + k] = __float2bfloat16(qkv_w[l]);
    } else if (idx < PREP_PROJ_END) {
        int l = idx - PREP_QKV_END; int k = l / 128, n = l % 128;
        g_wt[WT_PROJ + n * 128 + k] = __float2bfloat16(proj_w[l]);
    } else if (idx < PREP_FC1_END) {
        int l = idx - PREP_PROJ_END; int k = l / 512, n = l % 512;
        g_wt[WT_FC1 + n * 128 + k] = __float2bfloat16(fc1_w[l]);
    } else if (idx < PREP_FC2_END) {
        int l = idx - PREP_FC1_END; int k = l / 128, n = l % 128;
        g_wt[WT_FC2 + n * 512 + k] = __float2bfloat16(fc2_w[l]);
    } else {
        int r = idx - PREP_FC2_END;
        int h = r / (112 * 112);
        int rr = r % (112 * 112);
        int i = rr / 112, j = rr % 112;
        float v = 0.f;
        if (i < NTOK && j < NTOK) {
            int ti = i / 49, hi = (i / 7) % 7, wi = i % 7;
            int tj = j / 49, hj = (j / 7) % 7, wj = j % 7;
            int ridx = (ti - tj + 1) * 169 + (hi - hj + 6) * 13 + (wi - wj + 6);
            v = rpb[ridx * 4 + h];
        }
        g_biasNN[h * 112 * 112 + rr] = v;
    }
}

// window-layout row -> token row (shift/roll gather mapping)
__device__ __forceinline__ int win2tok(int row) {
    int bwin = row / NTOK, n = row % NTOK;
    int b = bwin >> 8, win = bwin & 255;
    int tw = win >> 6, hw = (win >> 3) & 7, ww = win & 7;
    int t0 = n / 49, r49 = n % 49, h0 = r49 / 7, w0 = r49 % 7;
    int tg = (tw * 2 + t0 + 1) & 7;
    int hg = hw * 7 + h0 + 3; if (hg >= 56) hg -= 56;
    int wg = ww * 7 + w0 + 3; if (wg >= 56) wg -= 56;
    return b * LTOK + (tg * 56 + hg) * 56 + wg;
}

// ---------------------------------------------------------------------------
// LN1 + shift + window partition -> bf16
// ---------------------------------------------------------------------------
__global__ void ln_gather_kernel(const float* __restrict__ x,
                                 const float* __restrict__ g,
                                 const float* __restrict__ bta,
                                 __nv_bfloat16* __restrict__ out) {
    int warp = threadIdx.x >> 5, lane = threadIdx.x & 31;
    int row = blockIdx.x * 8 + warp;
    const float* src = x + (size_t)win2tok(row) * CC;

    float v[4]; float s = 0.f;
#pragma unroll
    for (int k = 0; k < 4; k++) { v[k] = src[lane + 32 * k]; s += v[k]; }
#pragma unroll
    for (int o = 16; o > 0; o >>= 1) s += __shfl_xor_sync(0xffffffffu, s, o);
    float mean = s * (1.0f / CC);
    float q = 0.f;
#pragma unroll
    for (int k = 0; k < 4; k++) { float d = v[k] - mean; q += d * d; }
#pragma unroll
    for (int o = 16; o > 0; o >>= 1) q += __shfl_xor_sync(0xffffffffu, q, o);
    float rstd = rsqrtf(q * (1.0f / CC) + EPS);
    __nv_bfloat16* dst = out + (size_t)row * CC;
#pragma unroll
    for (int k = 0; k < 4; k++) {
        int c = lane + 32 * k;
        dst[c] = __float2bfloat16((v[k] - mean) * rstd * g[c] + bta[c]);
    }
}

// ---------------------------------------------------------------------------
// N-loop GEMM for K=128 (A resident). EPI: 0 bias, 1 bias+GELU. bf16 out.
// ---------------------------------------------------------------------------
#define NSTR 136
#define NL_TILE_BYTES (128 * NSTR * 2)
#define NL_SMEM (3 * NL_TILE_BYTES)

template <int NT, int EPI>
__global__ __launch_bounds__(256) void gemm_nloop_kernel(
        const __nv_bfloat16* __restrict__ A, const __nv_bfloat16* __restrict__ Wt,
        const float* __restrict__ bias, __nv_bfloat16* __restrict__ out) {
    extern __shared__ __align__(16) char smem[];
    __nv_bfloat16* sA = (__nv_bfloat16*)smem;

    int t = threadIdx.x;
    int warp = t >> 5, lane = t & 31;
    int wm = warp & 1, wn = warp >> 1;
    int gid = lane >> 2, tig = lane & 3;
    int m0 = blockIdx.x << 7;
    const int Np = NT * 128;

    {
        const __nv_bfloat16* Ag = A + (size_t)m0 * 128;
#pragma unroll
        for (int it = 0; it < 8; it++) {
            int c = t + (it << 8);
            int r = c >> 4, c8 = (c & 15) << 3;
            cp16(&sA[r * NSTR + c8], Ag + (size_t)r * 128 + c8);
        }
        __nv_bfloat16* sB0 = (__nv_bfloat16*)(smem + NL_TILE_BYTES);
#pragma unroll
        for (int it = 0; it < 8; it++) {
            int c = t + (it << 8);
            int r = c >> 4, c8 = (c & 15) << 3;
            cp16(&sB0[r * NSTR + c8], Wt + (size_t)r * 128 + c8);
        }
        cp_commit();
    }

    for (int nt = 0; nt < NT; nt++) {
        if (nt + 1 < NT) {
            __nv_bfloat16* sBn = (__nv_bfloat16*)(smem + NL_TILE_BYTES
                                                  + ((nt + 1) & 1) * NL_TILE_BYTES);
            const __nv_bfloat16* Bg = Wt + (size_t)(nt + 1) * 128 * 128;
#pragma unroll
            for (int it = 0; it < 8; it++) {
                int c = t + (it << 8);
                int r = c >> 4, c8 = (c & 15) << 3;
                cp16(&sBn[r * NSTR + c8], Bg + (size_t)r * 128 + c8);
            }
            cp_commit();
            cp_wait<1>();
        } else {
            cp_wait<0>();
        }
        __syncthreads();
        const __nv_bfloat16* sB = (const __nv_bfloat16*)(smem + NL_TILE_BYTES
                                                         + (nt & 1) * NL_TILE_BYTES);
        float acc[4][4][4];
#pragma unroll
        for (int mt = 0; mt < 4; mt++)
#pragma unroll
            for (int ntx = 0; ntx < 4; ntx++)
#pragma unroll
                for (int e = 0; e < 4; e++) acc[mt][ntx][e] = 0.f;

#pragma unroll
        for (int ks = 0; ks < 8; ks++) {
            int k0 = ks << 4;
            uint32_t af[4][4], bf[4][2];
#pragma unroll
            for (int mt = 0; mt < 4; mt++) {
                int base = (wm * 64 + mt * 16 + gid) * NSTR + k0 + tig * 2;
                af[mt][0] = *(const uint32_t*)&sA[base];
                af[mt][1] = *(const uint32_t*)&sA[base + 8 * NSTR];
                af[mt][2] = *(const uint32_t*)&sA[base + 8];
                af[mt][3] = *(const uint32_t*)&sA[base + 8 * NSTR + 8];
            }
#pragma unroll
            for (int ntx = 0; ntx < 4; ntx++) {
                int base = (wn * 32 + ntx * 8 + gid) * NSTR + k0 + tig * 2;
                bf[ntx][0] = *(const uint32_t*)&sB[base];
                bf[ntx][1] = *(const uint32_t*)&sB[base + 8];
            }
#pragma unroll
            for (int mt = 0; mt < 4; mt++)
#pragma unroll
                for (int ntx = 0; ntx < 4; ntx++)
                    mma16816(acc[mt][ntx], af[mt], bf[ntx]);
        }
        __syncthreads();

        int ncol0 = nt * 128;
#pragma unroll
        for (int mt = 0; mt < 4; mt++) {
            int row = m0 + wm * 64 + mt * 16 + gid;
#pragma unroll
            for (int ntx = 0; ntx < 4; ntx++) {
                int col = ncol0 + wn * 32 + ntx * 8 + tig * 2;
                float b0 = bias[col], b1 = bias[col + 1];
                float v00 = acc[mt][ntx][0] + b0, v01 = acc[mt][ntx][1] + b1;
                float v10 = acc[mt][ntx][2] + b0, v11 = acc[mt][ntx][3] + b1;
                if (EPI == 1) {
                    v00 = 0.5f * v00 * (1.0f + erff(v00 * 0.7071067811865475f));
                    v01 = 0.5f * v01 * (1.0f + erff(v01 * 0.7071067811865475f));
                    v10 = 0.5f * v10 * (1.0f + erff(v10 * 0.7071067811865475f));
                    v11 = 0.5f * v11 * (1.0f + erff(v11 * 0.7071067811865475f));
                }
                *(__nv_bfloat162*)(out + (size_t)row * Np + col) =
                    __floats2bfloat162_rn(v00, v01);
                *(__nv_bfloat162*)(out + (size_t)(row + 8) * Np + col) =
                    __floats2bfloat162_rn(v10, v11);
            }
        }
    }
}

// ---------------------------------------------------------------------------
// Pipelined HMMA GEMM (BK=32 double-buffered). EPI: 2 bias+resid (fp32 out),
// 3 bias+scatter-resid+LN2 (proj; bf16 lnout + fp32 x2out).
// ---------------------------------------------------------------------------
#define SSTR 40
#define STAGE_BYTES (2 * 128 * SSTR * 2)
#define GEMM_SMEM   (2 * STAGE_BYTES)
#define PROJ_SMEM   (128 * 132 * 4)

template <int EPI, int OUTBF>
__global__ __launch_bounds__(256) void gemm_mma_kernel(
        const __nv_bfloat16* __restrict__ A, const __nv_bfloat16* __restrict__ Wt,
        const float* __restrict__ bias, const float* __restrict__ resid,
        void* __restrict__ outv, int M, int Np, int K,
        const float* __restrict__ xres, const float* __restrict__ ln_g,
        const float* __restrict__ ln_b, float* __restrict__ x2out) {
    extern __shared__ __align__(16) char smem[];

    int t = threadIdx.x;
    int warp = t >> 5, lane = t & 31;
    int wm = warp & 1, wn = warp >> 1;
    int gid = lane >> 2, tig = lane & 3;
    int n0 = blockIdx.x << 7, m0 = blockIdx.y << 7;

    float acc[4][4][4];
#pragma unroll
    for (int mt = 0; mt < 4; mt++)
#pragma unroll
        for (int nt = 0; nt < 4; nt++)
#pragma unroll
            for (int e = 0; e < 4; e++) acc[mt][nt][e] = 0.f;

    int lr = t >> 2;
    int lc = (t & 3) << 3;

    const __nv_bfloat16* Ag = A + (size_t)(m0 + lr) * K + lc;
    const __nv_bfloat16* Bg = Wt + (size_t)(n0 + lr) * K + lc;
    int sa0 = (lr * SSTR + lc) * 2;
    int sa1 = ((lr + 64) * SSTR + lc) * 2;
    int nk = K >> 5;

    {
        char* st = smem;
        cp16(st + sa0, Ag);
        cp16(st + sa1, Ag + (size_t)64 * K);
        cp16(st + 10240 + sa0, Bg);
        cp16(st + 10240 + sa1, Bg + (size_t)64 * K);
        cp_commit();
    }

    for (int kc = 0; kc < nk; kc++) {
        if (kc + 1 < nk) {
            char* st = smem + ((kc + 1) & 1) * STAGE_BYTES;
            int kt = (kc + 1) << 5;
            cp16(st + sa0, Ag + kt);
            cp16(st + sa1, Ag + (size_t)64 * K + kt);
            cp16(st + 10240 + sa0, Bg + kt);
            cp16(st + 10240 + sa1, Bg + (size_t)64 * K + kt);
            cp_commit();
            cp_wait<1>();
        } else {
            cp_wait<0>();
        }
        __syncthreads();
        const __nv_bfloat16* sA = (const __nv_bfloat16*)(smem + (kc & 1) * STAGE_BYTES);
        const __nv_bfloat16* sB = sA + 128 * SSTR;
#pragma unroll
        for (int ks = 0; ks < 2; ks++) {
            int k0 = ks << 4;
            uint32_t af[4][4], bf[4][2];
#pragma unroll
            for (int mt = 0; mt < 4; mt++) {
                int base = (wm * 64 + mt * 16 + gid) * SSTR + k0 + tig * 2;
                af[mt][0] = *(const uint32_t*)&sA[base];
                af[mt][1] = *(const uint32_t*)&sA[base + 8 * SSTR];
                af[mt][2] = *(const uint32_t*)&sA[base + 8];
                af[mt][3] = *(const uint32_t*)&sA[base + 8 * SSTR + 8];
            }
#pragma unroll
            for (int nt = 0; nt < 4; nt++) {
                int base = (wn * 32 + nt * 8 + gid) * SSTR + k0 + tig * 2;
                bf[nt][0] = *(const uint32_t*)&sB[base];
                bf[nt][1] = *(const uint32_t*)&sB[base + 8];
            }
#pragma unroll
            for (int mt = 0; mt < 4; mt++)
#pragma unroll
                for (int nt = 0; nt < 4; nt++)
                    mma16816(acc[mt][nt], af[mt], bf[nt]);
        }
        __syncthreads();
    }

    if (EPI == 3) {
        float* sout = (float*)smem;
#pragma unroll
        for (int mt = 0; mt < 4; mt++) {
            int row = wm * 64 + mt * 16 + gid;
#pragma unroll
            for (int nt = 0; nt < 4; nt++) {
                int col = wn * 32 + nt * 8 + tig * 2;
                float b0 = bias[col], b1 = bias[col + 1];
                sout[row * 132 + col] = acc[mt][nt][0] + b0;
                sout[row * 132 + col + 1] = acc[mt][nt][1] + b1;
                sout[(row + 8) * 132 + col] = acc[mt][nt][2] + b0;
                sout[(row + 8) * 132 + col + 1] = acc[mt][nt][3] + b1;
            }
        }
        __syncthreads();
        __nv_bfloat16* lnout = (__nv_bfloat16*)outv;
#pragma unroll
        for (int i = 0; i < 16; i++) {
            int row = warp * 16 + i;
            int tr = win2tok(m0 + row);
            const float* xr = xres + (size_t)tr * CC;
            float v[4]; float s = 0.f;
#pragma unroll
            for (int k = 0; k < 4; k++) {
                int c = lane + 32 * k;
                v[k] = sout[row * 132 + c] + xr[c];
                s += v[k];
            }
            float* dx2 = x2out + (size_t)tr * CC;
#pragma unroll
            for (int k = 0; k < 4; k++) dx2[lane + 32 * k] = v[k];
#pragma unroll
            for (int o = 16; o > 0; o >>= 1) s += __shfl_xor_sync(0xffffffffu, s, o);
            float mean = s * (1.0f / CC);
            float q = 0.f;
#pragma unroll
            for (int k = 0; k < 4; k++) { float d = v[k] - mean; q += d * d; }
#pragma unroll
            for (int o = 16; o > 0; o >>= 1) q += __shfl_xor_sync(0xffffffffu, q, o);
            float rstd = rsqrtf(q * (1.0f / CC) + EPS);
            __nv_bfloat16* dst = lnout + (size_t)tr * CC;
#pragma unroll
            for (int k = 0; k < 4; k++) {
                int c = lane + 32 * k;
                dst[c] = __float2bfloat16((v[k] - mean) * rstd * ln_g[c] + ln_b[c]);
            }
        }
        return;
    }

#pragma unroll
    for (int mt = 0; mt < 4; mt++) {
        int row = m0 + wm * 64 + mt * 16 + gid;
#pragma unroll
        for (int nt = 0; nt < 4; nt++) {
            int col = n0 + wn * 32 + nt * 8 + tig * 2;
            float b0 = bias[col], b1 = bias[col + 1];
            float v00 = acc[mt][nt][0] + b0, v01 = acc[mt][nt][1] + b1;
            float v10 = acc[mt][nt][2] + b0, v11 = acc[mt][nt][3] + b1;
            size_t o0 = (size_t)row * Np + col;
            size_t o1 = (size_t)(row + 8) * Np + col;
            if (EPI == 2) {
                float2 r0 = *(const float2*)(resid + o0);
                float2 r1 = *(const float2*)(resid + o1);
                v00 += r0.x; v01 += r0.y; v10 += r1.x; v11 += r1.y;
            }
            if (OUTBF) {
                __nv_bfloat16* op = (__nv_bfloat16*)outv;
                *(__nv_bfloat162*)(op + o0) = __floats2bfloat162_rn(v00, v01);
                *(__nv_bfloat162*)(op + o1) = __floats2bfloat162_rn(v10, v11);
            } else {
                float* op = (float*)outv;
                *(float2*)(op + o0) = make_float2(v00, v01);
                *(float2*)(op + o1) = make_float2(v10, v11);
            }
        }
    }
}

// ---------------------------------------------------------------------------
// HMMA attention v2: 224 threads (7 warps, one 16-row m-tile each).
// P stays in registers (QK C-frag layout == PV A-frag layout) — no P smem,
// no inter-phase sync.
// ---------------------------------------------------------------------------
#define QSTR 40
#define PSTR 120
#define ASMEM_ELEMS (2 * 112 * QSTR + 32 * PSTR)   // 12800 bf16 = 25.6 KB

__global__ __launch_bounds__(224) void attn_mma_kernel(
        const __nv_bfloat16* __restrict__ qkv, __nv_bfloat16* __restrict__ out) {
    extern __shared__ __align__(16) __nv_bfloat16 asmem[];
    __nv_bfloat16* sQ  = asmem;               // [112][QSTR]
    __nv_bfloat16* sK  = sQ + 112 * QSTR;     // [112][QSTR]
    __nv_bfloat16* sVt = sK + 112 * QSTR;     // [32][PSTR]
    __shared__ int sreg[112];

    int bwin = blockIdx.x >> 2, head = blockIdx.x & 3;
    int tid = threadIdx.x, warp = tid >> 5, lane = tid & 31;
    int gid = lane >> 2, tig = lane & 3;

    size_t base = (size_t)bwin * NTOK * 384 + head * 32;
    // Q,K rows 0..97 (98*16 = 7*224 iterations exactly)
#pragma unroll
    for (int it = 0; it < 7; it++) {
        int idx = tid + it * 224;
        int n = idx >> 4, d2 = (idx & 15) << 1;
        size_t o = base + (size_t)n * 384 + d2;
        *(uint32_t*)&sQ[n * QSTR + d2] = *(const uint32_t*)(qkv + o);
        *(uint32_t*)&sK[n * QSTR + d2] = *(const uint32_t*)(qkv + o + 128);
    }
    // V transposed (98*32 = 14*224)
#pragma unroll
    for (int it = 0; it < 14; it++) {
        int idx = tid + it * 224;
        int n = idx >> 5, d = idx & 31;
        sVt[d * PSTR + n] = qkv[base + (size_t)n * 384 + 256 + d];
    }
    // zero pads: Q/K rows 98..111 (14*16 = 224)
    {
        int idx = tid;
        int r = 98 + (idx >> 4), d2 = (idx & 15) << 1;
        *(uint32_t*)&sQ[r * QSTR + d2] = 0u;
        *(uint32_t*)&sK[r * QSTR + d2] = 0u;
    }
    // Vt pad cols (32*14 = 448 = 2*224)
#pragma unroll
    for (int it = 0; it < 2; it++) {
        int idx = tid + it * 224;
        int d = idx / 14, n = 98 + idx % 14;
        sVt[d * PSTR + n] = __float2bfloat16(0.f);
    }
    if (tid < 112) {
        int v = 0;
        if (tid < 98) {
            int win = bwin & 255;
            int tw = win >> 6, hw = (win >> 3) & 7, ww = win & 7;
            int t0 = tid / 49, r = tid % 49, h0 = r / 7, w0 = r % 7;
            int tg = tw * 2 + t0, hg = hw * 7 + h0, wg = ww * 7 + w0;
            int rt = tg < 6 ? 0 : (tg < 7 ? 1 : 2);
            int rh = hg < 49 ? 0 : (hg < 53 ? 1 : 2);
            int rw = wg < 49 ? 0 : (wg < 53 ? 1 : 2);
            v = rt * 9 + rh * 3 + rw;
        }
        sreg[tid] = v;
    }
    __syncthreads();

    int mrow = warp << 4;
    float acc[14][4];
#pragma unroll
    for (int n = 0; n < 14; n++)
#pragma unroll
        for (int e = 0; e < 4; e++) acc[n][e] = 0.f;

    // S = Q K^T
#pragma unroll
    for (int ks = 0; ks < 2; ks++) {
        int k0 = ks << 4;
        uint32_t af[4];
        const __nv_bfloat16* qb = sQ + (mrow + gid) * QSTR + k0 + tig * 2;
        af[0] = *(const uint32_t*)qb;
        af[1] = *(const uint32_t*)(qb + 8 * QSTR);
        af[2] = *(const uint32_t*)(qb + 8);
        af[3] = *(const uint32_t*)(qb + 8 * QSTR + 8);
#pragma unroll
        for (int n = 0; n < 14; n++) {
            uint32_t bf[2];
            const __nv_bfloat16* kb = sK + (n * 8 + gid) * QSTR + k0 + tig * 2;
            bf[0] = *(const uint32_t*)kb;
            bf[1] = *(const uint32_t*)(kb + 8);
            mma16816(acc[n], af, bf);
        }
    }

    // bias + mask + softmax
    int r0 = mrow + gid, r1 = r0 + 8;
    const float* bh = g_biasNN + head * (112 * 112);
    int ri0 = sreg[r0], ri1 = sreg[r1];
    float mx0 = -1e30f, mx1 = -1e30f;
#pragma unroll
    for (int n = 0; n < 14; n++) {
        int col = n * 8 + tig * 2;
        float2 b0 = *(const float2*)(bh + r0 * 112 + col);
        float2 b1 = *(const float2*)(bh + r1 * 112 + col);
        int rj0 = sreg[col], rj1 = sreg[col + 1];
        acc[n][0] = acc[n][0] * SCALE + b0.x + (ri0 != rj0 ? -100.f : 0.f);
        acc[n][1] = acc[n][1] * SCALE + b0.y + (ri0 != rj1 ? -100.f : 0.f);
        acc[n][2] = acc[n][2] * SCALE + b1.x + (ri1 != rj0 ? -100.f : 0.f);
        acc[n][3] = acc[n][3] * SCALE + b1.y + (ri1 != rj1 ? -100.f : 0.f);
        if (col < 98)     { mx0 = fmaxf(mx0, acc[n][0]); mx1 = fmaxf(mx1, acc[n][2]); }
        if (col + 1 < 98) { mx0 = fmaxf(mx0, acc[n][1]); mx1 = fmaxf(mx1, acc[n][3]); }
    }
    mx0 = fmaxf(mx0, __shfl_xor_sync(0xffffffffu, mx0, 1));
    mx0 = fmaxf(mx0, __shfl_xor_sync(0xffffffffu, mx0, 2));
    mx1 = fmaxf(mx1, __shfl_xor_sync(0xffffffffu, mx1, 1));
    mx1 = fmaxf(mx1, __shfl_xor_sync(0xffffffffu, mx1, 2));
    float sm0 = 0.f, sm1 = 0.f;
#pragma unroll
    for (int n = 0; n < 14; n++) {
        int col = n * 8 + tig * 2;
        float e0 = (col < 98)     ? __expf(acc[n][0] - mx0) : 0.f;
        float e1 = (col + 1 < 98) ? __expf(acc[n][1] - mx0) : 0.f;
        float e2 = (col < 98)     ? __expf(acc[n][2] - mx1) : 0.f;
        float e3 = (col + 1 < 98) ? __expf(acc[n][3] - mx1) : 0.f;
        acc[n][0] = e0; acc[n][1] = e1; acc[n][2] = e2; acc[n][3] = e3;
        sm0 += e0 + e1; sm1 += e2 + e3;
    }
    sm0 += __shfl_xor_sync(0xffffffffu, sm0, 1);
    sm0 += __shfl_xor_sync(0xffffffffu, sm0, 2);
    sm1 += __shfl_xor_sync(0xffffffffu, sm1, 1);
    sm1 += __shfl_xor_sync(0xffffffffu, sm1, 2);
    float inv0 = 1.f / sm0, inv1 = 1.f / sm1;

    // pack P into A-fragments (register-resident):
    // plo[n] = P[r0][n*8+tig*2..+1], phi[n] = P[r1][...]
    uint32_t plo[14], phi[14];
#pragma unroll
    for (int n = 0; n < 14; n++) {
        plo[n] = packbf2(acc[n][0] * inv0, acc[n][1] * inv0);
        phi[n] = packbf2(acc[n][2] * inv1, acc[n][3] * inv1);
    }

    // O = P V  (A-frags straight from plo/phi)
    float oacc[4][4];
#pragma unroll
    for (int n = 0; n < 4; n++)
#pragma unroll
        for (int e = 0; e < 4; e++) oacc[n][e] = 0.f;
#pragma unroll
    for (int ks = 0; ks < 7; ks++) {
        int k0 = ks << 4;
        uint32_t af[4];
        af[0] = plo[2 * ks];
        af[1] = phi[2 * ks];
        af[2] = plo[2 * ks + 1];
        af[3] = phi[2 * ks + 1];
#pragma unroll
        for (int n = 0; n < 4; n++) {
            uint32_t bf[2];
            const __nv_bfloat16* vb = sVt + (n * 8 + gid) * PSTR + k0 + tig * 2;
            bf[0] = *(const uint32_t*)vb;
            bf[1] = *(const uint32_t*)(vb + 8);
            mma16816(oacc[n], af, bf);
        }
    }
    size_t obase = (size_t)bwin * NTOK * CC + head * 32;
#pragma unroll
    for (int n = 0; n < 4; n++) {
        int col = n * 8 + tig * 2;
        if (r0 < 98)
            *(__nv_bfloat162*)(out + obase + (size_t)r0 * CC + col) =
                __floats2bfloat162_rn(oacc[n][0], oacc[n][1]);
        if (r1 < 98)
            *(__nv_bfloat162*)(out + obase + (size_t)r1 * CC + col) =
                __floats2bfloat162_rn(oacc[n][2], oacc[n][3]);
    }
}

// ---------------------------------------------------------------------------
// Launch
// ---------------------------------------------------------------------------
extern "C" void kernel_launch(void* const* d_in, const int* in_sizes, int n_in,
                              void* d_out, int out_size) {
    const float* x       = (const float*)d_in[0];
    const float* norm1_g = (const float*)d_in[1];
    const float* norm1_b = (const float*)d_in[2];
    const float* qkv_w   = (const float*)d_in[3];
    const float* qkv_b   = (const float*)d_in[4];
    const float* proj_w  = (const float*)d_in[5];
    const float* proj_b  = (const float*)d_in[6];
    const float* rpb     = (const float*)d_in[7];
    const float* norm2_g = (const float*)d_in[8];
    const float* norm2_b = (const float*)d_in[9];
    const float* fc1_w   = (const float*)d_in[10];
    const float* fc1_b   = (const float*)d_in[11];
    const float* fc2_w   = (const float*)d_in[12];
    const float* fc2_b   = (const float*)d_in[13];
    float* outp = (float*)d_out;

    __nv_bfloat16 *bh1, *bh2, *bh3, *wt;
    float *bufB;
    cudaGetSymbolAddress((void**)&bh1, g_bh1);
    cudaGetSymbolAddress((void**)&bh2, g_bh2);
    cudaGetSymbolAddress((void**)&bh3, g_bh3);
    cudaGetSymbolAddress((void**)&wt, g_wt);
    cudaGetSymbolAddress((void**)&bufB, g_bufB);

    cudaFuncSetAttribute(attn_mma_kernel, cudaFuncAttributeMaxDynamicSharedMemorySize,
                         ASMEM_ELEMS * 2);
    cudaFuncSetAttribute(gemm_mma_kernel<3, 1>,
                         cudaFuncAttributeMaxDynamicSharedMemorySize, PROJ_SMEM);
    cudaFuncSetAttribute(gemm_nloop_kernel<3, 0>,
                         cudaFuncAttributeMaxDynamicSharedMemorySize, NL_SMEM);
    cudaFuncSetAttribute(gemm_nloop_kernel<4, 1>,
                         cudaFuncAttributeMaxDynamicSharedMemorySize, NL_SMEM);

    // combined prep
    prep_kernel<<<(PREP_TOTAL + 255) / 256, 256>>>(qkv_w, proj_w, fc1_w, fc2_w, rpb);

    // LN1 + shift + partition -> bh2 (bf16, window layout)
    ln_gather_kernel<<<MROWS / 8, 256>>>(x, norm1_g, norm1_b, bh2);

    // QKV GEMM (A-resident n-loop) -> bh1 bf16 [M,384]
    gemm_nloop_kernel<3, 0><<<MROWS / 128, 256, NL_SMEM>>>(
        bh2, wt + WT_QKV, qkv_b, bh1);

    // attention -> bh2 bf16 (window layout)
    attn_mma_kernel<<<BWIN * 4, 224, ASMEM_ELEMS * 2>>>(bh1, bh2);

    // proj GEMM fused with scatter + residual + LN2 -> bh3 (bf16), bufB (x2)
    {
        dim3 grid(1, MROWS / 128);
        gemm_mma_kernel<3, 1><<<grid, 256, PROJ_SMEM>>>(
            bh2, wt + WT_PROJ, proj_b, nullptr, bh3, MROWS, 128, 128,
            x, norm2_g, norm2_b, bufB);
    }

    // FC1 + GELU (A-resident n-loop) -> bh1 bf16 [M,512]
    gemm_nloop_kernel<4, 1><<<MROWS / 128, 256, NL_SMEM>>>(
        bh3, wt + WT_FC1, fc1_b, bh1);

    // FC2 + residual(x2) -> d_out fp32 (token layout)
    {
        dim3 grid(1, MROWS / 128);
        gemm_mma_kernel<2, 0><<<grid, 256, GEMM_SMEM>>>(
            bh1, wt + WT_FC2, fc2_b, bufB, outp, MROWS, 128, 512,
            nullptr, nullptr, nullptr, nullptr);
    }
}